// round 6
// baseline (speedup 1.0000x reference)
#include <cuda_runtime.h>
#include <math.h>

#define N_NODES 50000
#define N_EDGES 800000
#define H 128
#define G_RBF 50
#define NBINS 7
#define CUTOFF 6.0f
#define SSP_SHIFT 0.6931471805599453f
#define PI_F 3.14159265358979323846f

#define SCAN_BLOCKS ((N_NODES + 255) / 256)   // 196
#define AT_STRIDE 68    // 64 nodes + 4 pad (floats), rows stay 16B-aligned
#define TILE_N 64

// ---------------- scratch (no allocation allowed) ----------------
__device__ float g_v[N_NODES * H];
__device__ float g_vlin[N_NODES * H];
__device__ float g_agg[N_NODES * H];
__device__ float g_wtab[2 * NBINS * H];
// CSR scratch
__device__ int   g_cnt[N_NODES];
__device__ int   g_off[N_NODES + 1];
__device__ int   g_pos[N_NODES];
__device__ int   g_bsum[SCAN_BLOCKS];
__device__ int   g_jt[N_EDGES];     // j | (tbin << 27)
__device__ float g_cs[N_EDGES];     // cutoff gate C

__device__ __forceinline__ float sspf(float x) {
    return fmaxf(x, 0.0f) + log1pf(expf(-fabsf(x))) - SSP_SHIFT;
}

// ---------------- filter table: T[layer][tbin][h] ----------------
__global__ void table_kernel(const float* __restrict__ m0w0, const float* __restrict__ m0b0,
                             const float* __restrict__ m2w0, const float* __restrict__ m2b0,
                             const float* __restrict__ m0w1, const float* __restrict__ m0b1,
                             const float* __restrict__ m2w1, const float* __restrict__ m2b1,
                             float* __restrict__ wtab) {
    int l = blockIdx.x / NBINS;
    int t = blockIdx.x % NBINS;
    const float* m0w = l ? m0w1 : m0w0;
    const float* m0b = l ? m0b1 : m0b0;
    const float* m2w = l ? m2w1 : m2w0;
    const float* m2b = l ? m2b1 : m2b0;

    __shared__ float hs[H];
    int h = threadIdx.x;

    const float step = CUTOFF / (float)(G_RBF - 1);
    const float coeff = -0.5f / (step * step);
    float acc = m0b[h];
#pragma unroll 10
    for (int g = 0; g < G_RBF; g++) {
        float off = step * (float)g;
        float dd = (float)t - off;
        acc += expf(coeff * dd * dd) * m0w[g * H + h];
    }
    hs[h] = sspf(acc);
    __syncthreads();

    float o = m2b[h];
#pragma unroll 16
    for (int k = 0; k < H; k++) o += hs[k] * m2w[k * H + h];
    wtab[(l * NBINS + t) * H + h] = o;
}

// ---------------- CSR build ----------------
__global__ void zero_cnt_kernel(int* __restrict__ cnt) {
    int i = blockIdx.x * blockDim.x + threadIdx.x;
    if (i < N_NODES) cnt[i] = 0;
}

__global__ void hist_kernel(const int* __restrict__ ei, int* __restrict__ cnt) {
    int e = blockIdx.x * blockDim.x + threadIdx.x;
    if (e < N_EDGES) atomicAdd(&cnt[ei[N_EDGES + e]], 1);
}

__global__ void scan1_kernel(const int* __restrict__ cnt, int* __restrict__ off,
                             int* __restrict__ bsum) {
    __shared__ int s[256];
    int t = threadIdx.x;
    int i = blockIdx.x * 256 + t;
    int v = (i < N_NODES) ? cnt[i] : 0;
    s[t] = v;
    __syncthreads();
#pragma unroll
    for (int o = 1; o < 256; o <<= 1) {
        int x = (t >= o) ? s[t - o] : 0;
        __syncthreads();
        s[t] += x;
        __syncthreads();
    }
    if (i < N_NODES) off[i] = s[t] - v;  // exclusive within block
    if (t == 255) bsum[blockIdx.x] = s[255];
}

__global__ void scan2_kernel(int* __restrict__ bsum) {
    __shared__ int s[256];
    int t = threadIdx.x;
    int v = (t < SCAN_BLOCKS) ? bsum[t] : 0;
    s[t] = v;
    __syncthreads();
#pragma unroll
    for (int o = 1; o < 256; o <<= 1) {
        int x = (t >= o) ? s[t - o] : 0;
        __syncthreads();
        s[t] += x;
        __syncthreads();
    }
    if (t < SCAN_BLOCKS) bsum[t] = s[t] - v;  // exclusive
}

__global__ void scan3_kernel(int* __restrict__ off, const int* __restrict__ bsum,
                             int* __restrict__ pos) {
    int i = blockIdx.x * blockDim.x + threadIdx.x;
    if (i < N_NODES) {
        int o = off[i] + bsum[i >> 8];
        off[i] = o;
        pos[i] = o;
    }
    if (i == 0) off[N_NODES] = N_EDGES;
}

__global__ void scatter_kernel(const int* __restrict__ ei, const float* __restrict__ dist,
                               int* __restrict__ pos, int* __restrict__ jt,
                               float* __restrict__ cs) {
    int e = blockIdx.x * blockDim.x + threadIdx.x;
    if (e >= N_EDGES) return;
    int j = ei[e];
    int i = ei[N_EDGES + e];
    float d = dist[e];
    int tb = (int)d;
    if (tb > NBINS - 1) tb = NBINS - 1;
    float C = 0.5f * cosf(d * (PI_F / CUTOFF)) + 0.5f;
    int p = atomicAdd(&pos[i], 1);
    jt[p] = j | (tb << 27);
    cs[p] = C;
}

// ---------------- aggregate: agg[i] = sum_{e->i} vlin[j]*T[tb]*C ----------------
__global__ void __launch_bounds__(256) agg_kernel(const float* __restrict__ vlin,
                                                  const int* __restrict__ off,
                                                  const int* __restrict__ jt,
                                                  const float* __restrict__ cs,
                                                  const float* __restrict__ wtab,
                                                  float* __restrict__ agg) {
    __shared__ float4 ws[NBINS * 32];
    int tid = threadIdx.x;
    if (tid < NBINS * 32) ws[tid] = ((const float4*)wtab)[tid];
    __syncthreads();

    int node = blockIdx.x * 8 + (tid >> 5);
    if (node >= N_NODES) return;
    int lane = tid & 31;

    int s = off[node], e = off[node + 1];
    float4 acc = make_float4(0.f, 0.f, 0.f, 0.f);
    const float4* vlin4 = (const float4*)vlin;

    for (int base = s; base < e; base += 32) {
        int m = min(32, e - base);
        int mj = (lane < m) ? jt[base + lane] : 0;
        float mc = (lane < m) ? cs[base + lane] : 0.f;
        int t = 0;
        for (; t + 4 <= m; t += 4) {
            int jv0 = __shfl_sync(0xffffffffu, mj, t);
            int jv1 = __shfl_sync(0xffffffffu, mj, t + 1);
            int jv2 = __shfl_sync(0xffffffffu, mj, t + 2);
            int jv3 = __shfl_sync(0xffffffffu, mj, t + 3);
            float c0 = __shfl_sync(0xffffffffu, mc, t);
            float c1 = __shfl_sync(0xffffffffu, mc, t + 1);
            float c2 = __shfl_sync(0xffffffffu, mc, t + 2);
            float c3 = __shfl_sync(0xffffffffu, mc, t + 3);
            float4 x0 = __ldg(vlin4 + (size_t)(jv0 & 0x07FFFFFF) * 32 + lane);
            float4 x1 = __ldg(vlin4 + (size_t)(jv1 & 0x07FFFFFF) * 32 + lane);
            float4 x2 = __ldg(vlin4 + (size_t)(jv2 & 0x07FFFFFF) * 32 + lane);
            float4 x3 = __ldg(vlin4 + (size_t)(jv3 & 0x07FFFFFF) * 32 + lane);
            float4 w0 = ws[(jv0 >> 27) * 32 + lane];
            float4 w1 = ws[(jv1 >> 27) * 32 + lane];
            float4 w2 = ws[(jv2 >> 27) * 32 + lane];
            float4 w3 = ws[(jv3 >> 27) * 32 + lane];
            acc.x += x0.x * w0.x * c0; acc.y += x0.y * w0.y * c0;
            acc.z += x0.z * w0.z * c0; acc.w += x0.w * w0.w * c0;
            acc.x += x1.x * w1.x * c1; acc.y += x1.y * w1.y * c1;
            acc.z += x1.z * w1.z * c1; acc.w += x1.w * w1.w * c1;
            acc.x += x2.x * w2.x * c2; acc.y += x2.y * w2.y * c2;
            acc.z += x2.z * w2.z * c2; acc.w += x2.w * w2.w * c2;
            acc.x += x3.x * w3.x * c3; acc.y += x3.y * w3.y * c3;
            acc.z += x3.z * w3.z * c3; acc.w += x3.w * w3.w * c3;
        }
        for (; t < m; t++) {
            int jv = __shfl_sync(0xffffffffu, mj, t);
            float c = __shfl_sync(0xffffffffu, mc, t);
            float4 x = __ldg(vlin4 + (size_t)(jv & 0x07FFFFFF) * 32 + lane);
            float4 w = ws[(jv >> 27) * 32 + lane];
            acc.x += x.x * w.x * c;
            acc.y += x.y * w.y * c;
            acc.z += x.z * w.z * c;
            acc.w += x.w * w.w * c;
        }
    }
    ((float4*)agg)[(size_t)node * 32 + lane] = acc;
}

// ---------------- FFMA2 inner product core (W in smem, A in smem) ----------------
// acc: 4 nodes x 4 col-pairs. tx: 8-col group (16), ty: 4-node group (16).
__device__ __forceinline__ void mm_core(const float* At, const float* Ws,
                                        int tx, int ty, unsigned long long acc[4][4]) {
#pragma unroll 4
    for (int k = 0; k < H; k++) {
        float4 a4 = *(const float4*)(At + k * AT_STRIDE + ty * 4);
        const ulonglong2* wk = (const ulonglong2*)(Ws + k * H + tx * 8);
        ulonglong2 wlo = wk[0];
        ulonglong2 whi = wk[1];
        float av[4] = {a4.x, a4.y, a4.z, a4.w};
        unsigned long long wv[4] = {wlo.x, wlo.y, whi.x, whi.y};
#pragma unroll
        for (int i = 0; i < 4; i++) {
            unsigned long long ap;
            asm("mov.b64 %0, {%1, %1};" : "=l"(ap) : "f"(av[i]));
#pragma unroll
            for (int jj = 0; jj < 4; jj++)
                asm("fma.rn.f32x2 %0, %1, %2, %0;"
                    : "+l"(acc[i][jj]) : "l"(ap), "l"(wv[jj]));
        }
    }
}

__device__ __forceinline__ void unpack8(const unsigned long long a[4], float v[8]) {
#pragma unroll
    for (int jj = 0; jj < 4; jj++) {
        float lo, hi;
        asm("mov.b64 {%0, %1}, %2;" : "=f"(lo), "=f"(hi) : "l"(a[jj]));
        v[2 * jj] = lo;
        v[2 * jj + 1] = hi;
    }
}

#define ZERO_ACC(acc)                                        \
    _Pragma("unroll")                                        \
    for (int i = 0; i < 4; i++)                              \
        _Pragma("unroll")                                    \
        for (int jj = 0; jj < 4; jj++) acc[i][jj] = 0ull;

#define STAGE_W(Ws, W)                                           \
    for (int idx = tid; idx < (H * H) / 4; idx += 256)           \
        ((float4*)(Ws))[idx] = ((const float4*)(W))[idx];

// stage A tile [TILE_N nodes x 128 k] transposed: At[k][node]
#define STAGE_A(At, A, nb, n)                                             \
    for (int idx = tid; idx < TILE_N * 32; idx += 256) {                  \
        int r = idx & (TILE_N - 1), c = idx >> 6;                         \
        int gn = (nb) + r;                                                \
        float4 val = (gn < (n)) ? ((const float4*)(A))[(size_t)gn * 32 + c] \
                                : make_float4(0.f, 0.f, 0.f, 0.f);        \
        (At)[(4 * c + 0) * AT_STRIDE + r] = val.x;                        \
        (At)[(4 * c + 1) * AT_STRIDE + r] = val.y;                        \
        (At)[(4 * c + 2) * AT_STRIDE + r] = val.z;                        \
        (At)[(4 * c + 3) * AT_STRIDE + r] = val.w;                        \
    }

// ---------------- gemm0: v = z@iw+ib (written), vlin = v @ linW ----------------
__global__ void __launch_bounds__(256, 2) gemm0_fused(const float* __restrict__ z,
                                                      const float* __restrict__ iw,
                                                      const float* __restrict__ ib,
                                                      const float* __restrict__ linW,
                                                      float* __restrict__ vout,
                                                      float* __restrict__ vlin, int n) {
    extern __shared__ float sm[];
    float* Ws = sm;
    float* At = sm + H * H;
    int tid = threadIdx.x;
    int nb = blockIdx.x * TILE_N;

    STAGE_W(Ws, linW);
    // compute v tile from z, write v, stage transposed into At
    for (int idx = tid; idx < TILE_N * 32; idx += 256) {
        int r = idx & (TILE_N - 1), c = idx >> 6;
        int gn = nb + r;
        float4 val = make_float4(0.f, 0.f, 0.f, 0.f);
        if (gn < n) {
            float z0 = __ldg(z + gn * 3), z1 = __ldg(z + gn * 3 + 1), z2 = __ldg(z + gn * 3 + 2);
            float4 b  = __ldg((const float4*)ib + c);
            float4 w0 = __ldg((const float4*)iw + c);
            float4 w1 = __ldg((const float4*)iw + 32 + c);
            float4 w2 = __ldg((const float4*)iw + 64 + c);
            val.x = b.x + z0 * w0.x + z1 * w1.x + z2 * w2.x;
            val.y = b.y + z0 * w0.y + z1 * w1.y + z2 * w2.y;
            val.z = b.z + z0 * w0.z + z1 * w1.z + z2 * w2.z;
            val.w = b.w + z0 * w0.w + z1 * w1.w + z2 * w2.w;
            ((float4*)vout)[(size_t)gn * 32 + c] = val;
        }
        At[(4 * c + 0) * AT_STRIDE + r] = val.x;
        At[(4 * c + 1) * AT_STRIDE + r] = val.y;
        At[(4 * c + 2) * AT_STRIDE + r] = val.z;
        At[(4 * c + 3) * AT_STRIDE + r] = val.w;
    }
    __syncthreads();

    int tx = tid & 15, ty = tid >> 4;
    unsigned long long acc[4][4];
    ZERO_ACC(acc);
    mm_core(At, Ws, tx, ty, acc);

#pragma unroll
    for (int i = 0; i < 4; i++) {
        int gn = nb + ty * 4 + i;
        if (gn >= n) continue;
        float v[8];
        unpack8(acc[i], v);
        ((float4*)vlin)[(size_t)gn * 32 + tx * 2]     = make_float4(v[0], v[1], v[2], v[3]);
        ((float4*)vlin)[(size_t)gn * 32 + tx * 2 + 1] = make_float4(v[4], v[5], v[6], v[7]);
    }
}

// ---------------- fused node MLP: v += ssp(agg@W1+b1)@W2 + b2 ; opt vlin = v@linW ----------------
template <bool MAKE_VLIN>
__global__ void __launch_bounds__(256, 2) fused_mlp(const float* __restrict__ A,
                                                    const float* __restrict__ W1,
                                                    const float* __restrict__ b1,
                                                    const float* __restrict__ W2,
                                                    const float* __restrict__ b2,
                                                    float* __restrict__ v,
                                                    const float* __restrict__ linW,
                                                    float* __restrict__ vlin, int n) {
    extern __shared__ float sm[];
    float* Ws = sm;
    float* At = sm + H * H;
    __shared__ float bs1[H], bs2[H];

    int tid = threadIdx.x;
    if (tid < H) { bs1[tid] = b1[tid]; bs2[tid] = b2[tid]; }

    int nb = blockIdx.x * TILE_N;
    STAGE_W(Ws, W1);
    STAGE_A(At, A, nb, n);
    __syncthreads();

    int tx = tid & 15, ty = tid >> 4;
    unsigned long long acc[4][4];
    ZERO_ACC(acc);
    mm_core(At, Ws, tx, ty, acc);
    __syncthreads();

    // t1 = ssp(acc + b1) -> At (transposed: At[col][node]); stage W2
#pragma unroll
    for (int i = 0; i < 4; i++) {
        float t1[8];
        unpack8(acc[i], t1);
        int node = ty * 4 + i;
#pragma unroll
        for (int jj = 0; jj < 8; jj++) {
            int col = tx * 8 + jj;
            At[col * AT_STRIDE + node] = sspf(t1[jj] + bs1[col]);
        }
    }
    STAGE_W(Ws, W2);
    __syncthreads();

    ZERO_ACC(acc);
    mm_core(At, Ws, tx, ty, acc);
    __syncthreads();   // all At/Ws reads done before rewrite

    float newv[4][8];
#pragma unroll
    for (int i = 0; i < 4; i++) {
        int gn = nb + ty * 4 + i;
        float o[8];
        unpack8(acc[i], o);
        int cb = tx * 8;
        float4 r0, r1;
        if (gn < n) {
            r0 = ((const float4*)v)[(size_t)gn * 32 + tx * 2];
            r1 = ((const float4*)v)[(size_t)gn * 32 + tx * 2 + 1];
        } else {
            r0 = make_float4(0.f, 0.f, 0.f, 0.f);
            r1 = make_float4(0.f, 0.f, 0.f, 0.f);
        }
        o[0] += bs2[cb + 0] + r0.x; o[1] += bs2[cb + 1] + r0.y;
        o[2] += bs2[cb + 2] + r0.z; o[3] += bs2[cb + 3] + r0.w;
        o[4] += bs2[cb + 4] + r1.x; o[5] += bs2[cb + 5] + r1.y;
        o[6] += bs2[cb + 6] + r1.z; o[7] += bs2[cb + 7] + r1.w;
        if (gn < n) {
            ((float4*)v)[(size_t)gn * 32 + tx * 2]     = make_float4(o[0], o[1], o[2], o[3]);
            ((float4*)v)[(size_t)gn * 32 + tx * 2 + 1] = make_float4(o[4], o[5], o[6], o[7]);
        }
        if (MAKE_VLIN) {
#pragma unroll
            for (int jj = 0; jj < 8; jj++) newv[i][jj] = o[jj];
        }
    }

    if (MAKE_VLIN) {
        // stage new v transposed into At + linW into Ws, third GEMM: vlin = v_new @ linW
#pragma unroll
        for (int i = 0; i < 4; i++) {
            int node = ty * 4 + i;
#pragma unroll
            for (int jj = 0; jj < 8; jj++)
                At[(tx * 8 + jj) * AT_STRIDE + node] = newv[i][jj];
        }
        STAGE_W(Ws, linW);
        __syncthreads();

        ZERO_ACC(acc);
        mm_core(At, Ws, tx, ty, acc);

#pragma unroll
        for (int i = 0; i < 4; i++) {
            int gn = nb + ty * 4 + i;
            if (gn >= n) continue;
            float o[8];
            unpack8(acc[i], o);
            ((float4*)vlin)[(size_t)gn * 32 + tx * 2]     = make_float4(o[0], o[1], o[2], o[3]);
            ((float4*)vlin)[(size_t)gn * 32 + tx * 2 + 1] = make_float4(o[4], o[5], o[6], o[7]);
        }
    }
}

// ---------------- fused readout: out = ssp(v@u1+b1) @ u2 + b2  ([N,3]) ----------------
__global__ void __launch_bounds__(256, 2) fused_readout(const float* __restrict__ A,
                                                        const float* __restrict__ W1,
                                                        const float* __restrict__ b1,
                                                        const float* __restrict__ W2,
                                                        const float* __restrict__ b2,
                                                        float* __restrict__ out, int n) {
    extern __shared__ float sm[];
    float* Ws = sm;
    float* At = sm + H * H;
    __shared__ float bs1[H], ws2[H * 3];

    int tid = threadIdx.x;
    if (tid < H) bs1[tid] = b1[tid];
    for (int idx = tid; idx < H * 3; idx += 256) ws2[idx] = W2[idx];

    int nb = blockIdx.x * TILE_N;
    STAGE_W(Ws, W1);
    STAGE_A(At, A, nb, n);
    __syncthreads();

    int tx = tid & 15, ty = tid >> 4;
    unsigned long long acc[4][4];
    ZERO_ACC(acc);
    mm_core(At, Ws, tx, ty, acc);

    float u2loc[8][3];
#pragma unroll
    for (int jj = 0; jj < 8; jj++) {
        int col = tx * 8 + jj;
        u2loc[jj][0] = ws2[col * 3 + 0];
        u2loc[jj][1] = ws2[col * 3 + 1];
        u2loc[jj][2] = ws2[col * 3 + 2];
    }

#pragma unroll
    for (int i = 0; i < 4; i++) {
        float h[8];
        unpack8(acc[i], h);
        float p0 = 0.f, p1 = 0.f, p2 = 0.f;
        int cb = tx * 8;
#pragma unroll
        for (int jj = 0; jj < 8; jj++) {
            float x = sspf(h[jj] + bs1[cb + jj]);
            p0 += x * u2loc[jj][0];
            p1 += x * u2loc[jj][1];
            p2 += x * u2loc[jj][2];
        }
#pragma unroll
        for (int off = 8; off; off >>= 1) {
            p0 += __shfl_down_sync(0xffffffffu, p0, off, 16);
            p1 += __shfl_down_sync(0xffffffffu, p1, off, 16);
            p2 += __shfl_down_sync(0xffffffffu, p2, off, 16);
        }
        if (tx == 0) {
            int gn = nb + ty * 4 + i;
            if (gn < n) {
                out[gn * 3 + 0] = p0 + b2[0];
                out[gn * 3 + 1] = p1 + b2[1];
                out[gn * 3 + 2] = p2 + b2[2];
            }
        }
    }
}

// ---------------- launch ----------------
static const int GEMM_SMEM = (H * H + H * AT_STRIDE) * sizeof(float);   // 100352 B

extern "C" void kernel_launch(void* const* d_in, const int* in_sizes, int n_in,
                              void* d_out, int out_size) {
    const float* z        = (const float*)d_in[0];
    const float* dist     = (const float*)d_in[1];
    const int*   ei       = (const int*)d_in[2];
    const float* init_w   = (const float*)d_in[3];
    const float* init_b   = (const float*)d_in[4];
    const float* e_lin_w[2] = {(const float*)d_in[5],  (const float*)d_in[14]};
    const float* e_m0_w[2]  = {(const float*)d_in[6],  (const float*)d_in[15]};
    const float* e_m0_b[2]  = {(const float*)d_in[7],  (const float*)d_in[16]};
    const float* e_m2_w[2]  = {(const float*)d_in[8],  (const float*)d_in[17]};
    const float* e_m2_b[2]  = {(const float*)d_in[9],  (const float*)d_in[18]};
    const float* v_l1_w[2]  = {(const float*)d_in[10], (const float*)d_in[19]};
    const float* v_l1_b[2]  = {(const float*)d_in[11], (const float*)d_in[20]};
    const float* v_l2_w[2]  = {(const float*)d_in[12], (const float*)d_in[21]};
    const float* v_l2_b[2]  = {(const float*)d_in[13], (const float*)d_in[22]};
    const float* u_l1_w   = (const float*)d_in[23];
    const float* u_l1_b   = (const float*)d_in[24];
    const float* u_l2_w   = (const float*)d_in[25];
    const float* u_l2_b   = (const float*)d_in[26];
    float* out = (float*)d_out;

    float *v, *vlin, *agg, *wtab, *cs;
    int *cnt, *off, *pos, *bsum, *jt;
    cudaGetSymbolAddress((void**)&v,    g_v);
    cudaGetSymbolAddress((void**)&vlin, g_vlin);
    cudaGetSymbolAddress((void**)&agg,  g_agg);
    cudaGetSymbolAddress((void**)&wtab, g_wtab);
    cudaGetSymbolAddress((void**)&cnt,  g_cnt);
    cudaGetSymbolAddress((void**)&off,  g_off);
    cudaGetSymbolAddress((void**)&pos,  g_pos);
    cudaGetSymbolAddress((void**)&bsum, g_bsum);
    cudaGetSymbolAddress((void**)&jt,   g_jt);
    cudaGetSymbolAddress((void**)&cs,   g_cs);

    cudaFuncSetAttribute((const void*)gemm0_fused,
                         cudaFuncAttributeMaxDynamicSharedMemorySize, GEMM_SMEM);
    cudaFuncSetAttribute((const void*)fused_mlp<true>,
                         cudaFuncAttributeMaxDynamicSharedMemorySize, GEMM_SMEM);
    cudaFuncSetAttribute((const void*)fused_mlp<false>,
                         cudaFuncAttributeMaxDynamicSharedMemorySize, GEMM_SMEM);
    cudaFuncSetAttribute((const void*)fused_readout,
                         cudaFuncAttributeMaxDynamicSharedMemorySize, GEMM_SMEM);

    const int gemm_grid = (N_NODES + TILE_N - 1) / TILE_N;
    const int egrid = (N_EDGES + 255) / 256;
    const int ngrid = (N_NODES + 255) / 256;

    // index 3 (gemm0_fused) is the launch ncu profiles
    table_kernel<<<2 * NBINS, H>>>(e_m0_w[0], e_m0_b[0], e_m2_w[0], e_m2_b[0],    // 0
                                   e_m0_w[1], e_m0_b[1], e_m2_w[1], e_m2_b[1], wtab);
    zero_cnt_kernel<<<ngrid, 256>>>(cnt);                                         // 1
    hist_kernel<<<egrid, 256>>>(ei, cnt);                                         // 2
    gemm0_fused<<<gemm_grid, 256, GEMM_SMEM>>>(z, init_w, init_b, e_lin_w[0],     // 3 <- profiled
                                               v, vlin, N_NODES);
    scan1_kernel<<<SCAN_BLOCKS, 256>>>(cnt, off, bsum);                           // 4
    scan2_kernel<<<1, 256>>>(bsum);                                               // 5
    scan3_kernel<<<SCAN_BLOCKS, 256>>>(off, bsum, pos);                           // 6
    scatter_kernel<<<egrid, 256>>>(ei, dist, pos, jt, cs);                        // 7

    // layer 0 (fused_mlp also produces vlin for layer 1)
    agg_kernel<<<(N_NODES + 7) / 8, 256>>>(vlin, off, jt, cs, wtab, agg);         // 8
    fused_mlp<true><<<gemm_grid, 256, GEMM_SMEM>>>(agg, v_l1_w[0], v_l1_b[0],     // 9
                                                   v_l2_w[0], v_l2_b[0], v,
                                                   e_lin_w[1], vlin, N_NODES);
    // layer 1
    agg_kernel<<<(N_NODES + 7) / 8, 256>>>(vlin, off, jt, cs,                     // 10
                                           wtab + NBINS * H, agg);
    fused_mlp<false><<<gemm_grid, 256, GEMM_SMEM>>>(agg, v_l1_w[1], v_l1_b[1],    // 11
                                                    v_l2_w[1], v_l2_b[1], v,
                                                    nullptr, nullptr, N_NODES);
    // readout
    fused_readout<<<gemm_grid, 256, GEMM_SMEM>>>(v, u_l1_w, u_l1_b,               // 12
                                                 u_l2_w, u_l2_b, out, N_NODES);
}

// round 8
// speedup vs baseline: 1.3165x; 1.3165x over previous
#include <cuda_runtime.h>
#include <cuda_bf16.h>
#include <mma.h>
#include <math.h>
#include <stdint.h>

using namespace nvcuda;

#define N_NODES 50000
#define N_EDGES 800000
#define H 128
#define G_RBF 50
#define NBINS 7
#define CUTOFF 6.0f
#define SSP_SHIFT 0.6931471805599453f
#define PI_F 3.14159265358979323846f

#define SCAN_BLOCKS ((N_NODES + 255) / 256)   // 196
#define TILE_M 64
#define N_TILES ((N_NODES + TILE_M - 1) / TILE_M)   // 782
#define WL 136            // bf16 leading dim (128 + 8 pad)
#define OL 132            // f32 output leading dim (128 + 4 pad)
#define WIMG_U32 17408    // per-matrix packed image: hi(8704 u32) + lo(8704 u32)

// smem layout (bytes) for tcgemm
#define SM_AHI 0
#define SM_ALO (TILE_M * WL * 2)                 // 17408
#define SM_BHI (2 * TILE_M * WL * 2)             // 34816
#define SM_BLO (SM_BHI + H * WL * 2)             // 34816 + 34816
#define TCG_SMEM (SM_BHI + 2 * H * WL * 2)       // 104448

// ---------------- scratch (no allocation allowed) ----------------
__device__ float g_v[N_NODES * H];
__device__ float g_vlin[N_NODES * H];
__device__ float g_agg[N_NODES * H];
__device__ float g_wtab[2 * NBINS * H];
__device__ uint32_t g_wpk[7 * WIMG_U32];
// CSR scratch
__device__ int   g_cnt[N_NODES];
__device__ int   g_off[N_NODES + 1];
__device__ int   g_pos[N_NODES];
__device__ int   g_bsum[SCAN_BLOCKS];
__device__ int   g_jt[N_EDGES];
__device__ float g_cs[N_EDGES];

__device__ __forceinline__ float sspf(float x) {
    return fmaxf(x, 0.0f) + log1pf(expf(-fabsf(x))) - SSP_SHIFT;
}

__device__ __forceinline__ uint32_t pack_bf16x2(float x0, float x1) {
    __nv_bfloat16 h0 = __float2bfloat16_rn(x0);
    __nv_bfloat16 h1 = __float2bfloat16_rn(x1);
    return (uint32_t)__bfloat16_as_ushort(h0) |
           ((uint32_t)__bfloat16_as_ushort(h1) << 16);
}

// ---------------- W pre-split: f32 [128,128] -> col-major bf16 hi/lo image ----------------
// image layout (col_major for wmma matrix_b): element (k, n) at [n*WL + k], bf16
__global__ void wsplit_kernel(const float* __restrict__ w0, const float* __restrict__ w1,
                              const float* __restrict__ w2, const float* __restrict__ w3,
                              const float* __restrict__ w4, const float* __restrict__ w5,
                              const float* __restrict__ w6, uint32_t* __restrict__ wpk) {
    const float* ws[7] = {w0, w1, w2, w3, w4, w5, w6};
    int m = blockIdx.y;
    const float* W = ws[m];
    int t = blockIdx.x * 256 + threadIdx.x;   // 0..8191
    if (t >= 8192) return;
    int n = t & 127;          // output column
    int kp = t >> 7;          // k pair index, k = 2*kp
    float x0 = W[(2 * kp) * H + n];
    float x1 = W[(2 * kp + 1) * H + n];
    float h0 = __bfloat162float(__float2bfloat16_rn(x0));
    float h1 = __bfloat162float(__float2bfloat16_rn(x1));
    uint32_t* base = wpk + (size_t)m * WIMG_U32;
    base[(n * WL + 2 * kp) >> 1]        = pack_bf16x2(x0, x1);          // hi
    base[8704 + ((n * WL + 2 * kp) >> 1)] = pack_bf16x2(x0 - h0, x1 - h1); // lo
}

// ---------------- tensor-core GEMM pass: out = f(A@W + b) [+res] ----------------
// 3-term bf16 split via wmma m16n16k16 (portable HMMA, valid on compute_103)
template <bool BIAS, bool DOSSP, bool RES>
__global__ void __launch_bounds__(256, 2) tcgemm(const float* __restrict__ A,
                                                 const uint32_t* __restrict__ wpk,
                                                 const float* __restrict__ bias,
                                                 const float* __restrict__ res,
                                                 float* __restrict__ out, int n) {
    extern __shared__ char sm[];
    __shared__ float bsm[H];
    int tid = threadIdx.x;
    int nb = blockIdx.x * TILE_M;

    if (BIAS && tid < H) bsm[tid] = bias[tid];

    // stage B (pre-split, pre-laid-out): one contiguous 69632-byte copy
    {
        const float4* src = (const float4*)wpk;
        float4* dst = (float4*)(sm + SM_BHI);
        for (int i = tid; i < (2 * H * WL * 2) / 16; i += 256) dst[i] = src[i];
    }
    // stage A: split f32 -> bf16 hi/lo, row-major ldm WL
    for (int idx = tid; idx < TILE_M * 32; idx += 256) {
        int node = idx >> 5, c = idx & 31;    // k = 4c
        int gn = nb + node;
        float4 a = (gn < n) ? ((const float4*)A)[(size_t)gn * 32 + c]
                            : make_float4(0.f, 0.f, 0.f, 0.f);
        float hx = __bfloat162float(__float2bfloat16_rn(a.x));
        float hy = __bfloat162float(__float2bfloat16_rn(a.y));
        float hz = __bfloat162float(__float2bfloat16_rn(a.z));
        float hw = __bfloat162float(__float2bfloat16_rn(a.w));
        uint32_t hlo = pack_bf16x2(a.x, a.y), hhi = pack_bf16x2(a.z, a.w);
        uint32_t llo = pack_bf16x2(a.x - hx, a.y - hy), lhi = pack_bf16x2(a.z - hz, a.w - hw);
        uint32_t boff = 2 * (node * WL + 4 * c);   // 8-byte aligned
        *(uint2*)(sm + SM_AHI + boff) = make_uint2(hlo, hhi);
        *(uint2*)(sm + SM_ALO + boff) = make_uint2(llo, lhi);
    }
    __syncthreads();

    int wid = tid >> 5;
    int wrow = wid & 3;          // node group (16 nodes)
    int wcol = wid >> 2;         // col half (64 cols)

    const __nv_bfloat16* Ahi = (const __nv_bfloat16*)(sm + SM_AHI) + wrow * 16 * WL;
    const __nv_bfloat16* Alo = (const __nv_bfloat16*)(sm + SM_ALO) + wrow * 16 * WL;
    const __nv_bfloat16* Bhi = (const __nv_bfloat16*)(sm + SM_BHI);
    const __nv_bfloat16* Blo = (const __nv_bfloat16*)(sm + SM_BLO);

    wmma::fragment<wmma::accumulator, 16, 16, 16, float> acc[4];
#pragma unroll
    for (int t = 0; t < 4; t++) wmma::fill_fragment(acc[t], 0.0f);

#pragma unroll
    for (int ks = 0; ks < 8; ks++) {
        wmma::fragment<wmma::matrix_a, 16, 16, 16, __nv_bfloat16, wmma::row_major> ah, al;
        wmma::load_matrix_sync(ah, Ahi + ks * 16, WL);
        wmma::load_matrix_sync(al, Alo + ks * 16, WL);
#pragma unroll
        for (int t = 0; t < 4; t++) {
            int ncol = wcol * 64 + t * 16;
            wmma::fragment<wmma::matrix_b, 16, 16, 16, __nv_bfloat16, wmma::col_major> bh, bl;
            wmma::load_matrix_sync(bh, Bhi + ncol * WL + ks * 16, WL);
            wmma::load_matrix_sync(bl, Blo + ncol * WL + ks * 16, WL);
            wmma::mma_sync(acc[t], ah, bh, acc[t]);
            wmma::mma_sync(acc[t], ah, bl, acc[t]);
            wmma::mma_sync(acc[t], al, bh, acc[t]);
        }
    }

    __syncthreads();   // all warps done reading A/B; overlay output on A region
    float* osm = (float*)(sm + SM_AHI);
#pragma unroll
    for (int t = 0; t < 4; t++)
        wmma::store_matrix_sync(osm + wrow * 16 * OL + wcol * 64 + t * 16,
                                acc[t], OL, wmma::mem_row_major);
    __syncthreads();

    // epilogue: thread -> (node = tid/4, 32-col group = (tid&3)*32)
    {
        int node = tid >> 2;
        int cb = (tid & 3) * 32;
        int gn = nb + node;
        if (gn < n) {
            const float* ip = osm + node * OL + cb;
            float* op = out + (size_t)gn * H + cb;
            const float4* rp = RES ? (const float4*)(res + (size_t)gn * H + cb) : nullptr;
#pragma unroll
            for (int i = 0; i < 8; i++) {
                float4 o;
                o.x = ip[4 * i + 0]; o.y = ip[4 * i + 1];
                o.z = ip[4 * i + 2]; o.w = ip[4 * i + 3];
                if (BIAS) {
                    o.x += bsm[cb + 4 * i + 0]; o.y += bsm[cb + 4 * i + 1];
                    o.z += bsm[cb + 4 * i + 2]; o.w += bsm[cb + 4 * i + 3];
                }
                if (DOSSP) { o.x = sspf(o.x); o.y = sspf(o.y); o.z = sspf(o.z); o.w = sspf(o.w); }
                if (RES) {
                    float4 r = rp[i];
                    o.x += r.x; o.y += r.y; o.z += r.z; o.w += r.w;
                }
                ((float4*)op)[i] = o;
            }
        }
    }
}

// ---------------- filter table ----------------
__global__ void table_kernel(const float* __restrict__ m0w0, const float* __restrict__ m0b0,
                             const float* __restrict__ m2w0, const float* __restrict__ m2b0,
                             const float* __restrict__ m0w1, const float* __restrict__ m0b1,
                             const float* __restrict__ m2w1, const float* __restrict__ m2b1,
                             float* __restrict__ wtab) {
    int l = blockIdx.x / NBINS;
    int t = blockIdx.x % NBINS;
    const float* m0w = l ? m0w1 : m0w0;
    const float* m0b = l ? m0b1 : m0b0;
    const float* m2w = l ? m2w1 : m2w0;
    const float* m2b = l ? m2b1 : m2b0;
    __shared__ float hs[H];
    int h = threadIdx.x;
    const float step = CUTOFF / (float)(G_RBF - 1);
    const float coeff = -0.5f / (step * step);
    float acc = m0b[h];
#pragma unroll 10
    for (int g = 0; g < G_RBF; g++) {
        float dd = (float)t - step * (float)g;
        acc += expf(coeff * dd * dd) * m0w[g * H + h];
    }
    hs[h] = sspf(acc);
    __syncthreads();
    float o = m2b[h];
#pragma unroll 16
    for (int k = 0; k < H; k++) o += hs[k] * m2w[k * H + h];
    wtab[(l * NBINS + t) * H + h] = o;
}

// ---------------- init: v = z @ init_w + init_b ----------------
__global__ void init_kernel(const float* __restrict__ z, const float* __restrict__ iw,
                            const float* __restrict__ ib, float* __restrict__ v) {
    int g = blockIdx.x * blockDim.x + threadIdx.x;
    if (g >= N_NODES * 32) return;
    int nn = g >> 5, c4 = g & 31;
    float4 b = ((const float4*)ib)[c4];
    float z0 = z[nn * 3 + 0], z1 = z[nn * 3 + 1], z2 = z[nn * 3 + 2];
    float4 w0 = ((const float4*)iw)[c4];
    float4 w1 = ((const float4*)iw)[32 + c4];
    float4 w2 = ((const float4*)iw)[64 + c4];
    float4 o;
    o.x = b.x + z0 * w0.x + z1 * w1.x + z2 * w2.x;
    o.y = b.y + z0 * w0.y + z1 * w1.y + z2 * w2.y;
    o.z = b.z + z0 * w0.z + z1 * w1.z + z2 * w2.z;
    o.w = b.w + z0 * w0.w + z1 * w1.w + z2 * w2.w;
    ((float4*)v)[nn * 32 + c4] = o;
}

// ---------------- CSR build ----------------
__global__ void zero_cnt_kernel(int* __restrict__ cnt) {
    int i = blockIdx.x * blockDim.x + threadIdx.x;
    if (i < N_NODES) cnt[i] = 0;
}
__global__ void hist_kernel(const int* __restrict__ ei, int* __restrict__ cnt) {
    int e = blockIdx.x * blockDim.x + threadIdx.x;
    if (e < N_EDGES) atomicAdd(&cnt[ei[N_EDGES + e]], 1);
}
__global__ void scan1_kernel(const int* __restrict__ cnt, int* __restrict__ off,
                             int* __restrict__ bsum) {
    __shared__ int s[256];
    int t = threadIdx.x;
    int i = blockIdx.x * 256 + t;
    int v = (i < N_NODES) ? cnt[i] : 0;
    s[t] = v;
    __syncthreads();
#pragma unroll
    for (int o = 1; o < 256; o <<= 1) {
        int x = (t >= o) ? s[t - o] : 0;
        __syncthreads();
        s[t] += x;
        __syncthreads();
    }
    if (i < N_NODES) off[i] = s[t] - v;
    if (t == 255) bsum[blockIdx.x] = s[255];
}
__global__ void scan2_kernel(int* __restrict__ bsum) {
    __shared__ int s[256];
    int t = threadIdx.x;
    int v = (t < SCAN_BLOCKS) ? bsum[t] : 0;
    s[t] = v;
    __syncthreads();
#pragma unroll
    for (int o = 1; o < 256; o <<= 1) {
        int x = (t >= o) ? s[t - o] : 0;
        __syncthreads();
        s[t] += x;
        __syncthreads();
    }
    if (t < SCAN_BLOCKS) bsum[t] = s[t] - v;
}
__global__ void scan3_kernel(int* __restrict__ off, const int* __restrict__ bsum,
                             int* __restrict__ pos) {
    int i = blockIdx.x * blockDim.x + threadIdx.x;
    if (i < N_NODES) {
        int o = off[i] + bsum[i >> 8];
        off[i] = o;
        pos[i] = o;
    }
    if (i == 0) off[N_NODES] = N_EDGES;
}
__global__ void scatter_kernel(const int* __restrict__ ei, const float* __restrict__ dist,
                               int* __restrict__ pos, int* __restrict__ jt,
                               float* __restrict__ cs) {
    int e = blockIdx.x * blockDim.x + threadIdx.x;
    if (e >= N_EDGES) return;
    int j = ei[e];
    int i = ei[N_EDGES + e];
    float d = dist[e];
    int tb = (int)d;
    if (tb > NBINS - 1) tb = NBINS - 1;
    float C = 0.5f * cosf(d * (PI_F / CUTOFF)) + 0.5f;
    int p = atomicAdd(&pos[i], 1);
    jt[p] = j | (tb << 27);
    cs[p] = C;
}

// ---------------- aggregate ----------------
__global__ void __launch_bounds__(256) agg_kernel(const float* __restrict__ vlin,
                                                  const int* __restrict__ off,
                                                  const int* __restrict__ jt,
                                                  const float* __restrict__ cs,
                                                  const float* __restrict__ wtab,
                                                  float* __restrict__ agg) {
    __shared__ float4 ws[NBINS * 32];
    int tid = threadIdx.x;
    if (tid < NBINS * 32) ws[tid] = ((const float4*)wtab)[tid];
    __syncthreads();

    int node = blockIdx.x * 8 + (tid >> 5);
    if (node >= N_NODES) return;
    int lane = tid & 31;
    int s = off[node], e = off[node + 1];
    float4 acc = make_float4(0.f, 0.f, 0.f, 0.f);
    const float4* vlin4 = (const float4*)vlin;

    for (int base = s; base < e; base += 32) {
        int m = min(32, e - base);
        int mj = (lane < m) ? jt[base + lane] : 0;
        float mc = (lane < m) ? cs[base + lane] : 0.f;
        int t = 0;
        for (; t + 4 <= m; t += 4) {
            int jv0 = __shfl_sync(0xffffffffu, mj, t);
            int jv1 = __shfl_sync(0xffffffffu, mj, t + 1);
            int jv2 = __shfl_sync(0xffffffffu, mj, t + 2);
            int jv3 = __shfl_sync(0xffffffffu, mj, t + 3);
            float c0 = __shfl_sync(0xffffffffu, mc, t);
            float c1 = __shfl_sync(0xffffffffu, mc, t + 1);
            float c2 = __shfl_sync(0xffffffffu, mc, t + 2);
            float c3 = __shfl_sync(0xffffffffu, mc, t + 3);
            float4 x0 = __ldg(vlin4 + (size_t)(jv0 & 0x07FFFFFF) * 32 + lane);
            float4 x1 = __ldg(vlin4 + (size_t)(jv1 & 0x07FFFFFF) * 32 + lane);
            float4 x2 = __ldg(vlin4 + (size_t)(jv2 & 0x07FFFFFF) * 32 + lane);
            float4 x3 = __ldg(vlin4 + (size_t)(jv3 & 0x07FFFFFF) * 32 + lane);
            float4 w0 = ws[(jv0 >> 27) * 32 + lane];
            float4 w1 = ws[(jv1 >> 27) * 32 + lane];
            float4 w2 = ws[(jv2 >> 27) * 32 + lane];
            float4 w3 = ws[(jv3 >> 27) * 32 + lane];
            acc.x += x0.x * w0.x * c0; acc.y += x0.y * w0.y * c0;
            acc.z += x0.z * w0.z * c0; acc.w += x0.w * w0.w * c0;
            acc.x += x1.x * w1.x * c1; acc.y += x1.y * w1.y * c1;
            acc.z += x1.z * w1.z * c1; acc.w += x1.w * w1.w * c1;
            acc.x += x2.x * w2.x * c2; acc.y += x2.y * w2.y * c2;
            acc.z += x2.z * w2.z * c2; acc.w += x2.w * w2.w * c2;
            acc.x += x3.x * w3.x * c3; acc.y += x3.y * w3.y * c3;
            acc.z += x3.z * w3.z * c3; acc.w += x3.w * w3.w * c3;
        }
        for (; t < m; t++) {
            int jv = __shfl_sync(0xffffffffu, mj, t);
            float c = __shfl_sync(0xffffffffu, mc, t);
            float4 x = __ldg(vlin4 + (size_t)(jv & 0x07FFFFFF) * 32 + lane);
            float4 w = ws[(jv >> 27) * 32 + lane];
            acc.x += x.x * w.x * c;
            acc.y += x.y * w.y * c;
            acc.z += x.z * w.z * c;
            acc.w += x.w * w.w * c;
        }
    }
    ((float4*)agg)[(size_t)node * 32 + lane] = acc;
}

// ---------------- readout: out = h @ u2 + b2 ----------------
__global__ void __launch_bounds__(256) readout_kernel(const float* __restrict__ hbuf,
                                                      const float* __restrict__ w2,
                                                      const float* __restrict__ b2,
                                                      float* __restrict__ out) {
    __shared__ float ws[H * 3];
    int tid = threadIdx.x;
    for (int idx = tid; idx < H * 3; idx += 256) ws[idx] = w2[idx];
    __syncthreads();

    int g = blockIdx.x * 256 + tid;
    int node = g >> 5;
    if (node >= N_NODES) return;
    int lane = g & 31;
    float4 h = ((const float4*)hbuf)[node * 32 + lane];
    int k0 = lane * 4;
    float s0 = h.x * ws[k0 * 3 + 0] + h.y * ws[(k0 + 1) * 3 + 0] +
               h.z * ws[(k0 + 2) * 3 + 0] + h.w * ws[(k0 + 3) * 3 + 0];
    float s1 = h.x * ws[k0 * 3 + 1] + h.y * ws[(k0 + 1) * 3 + 1] +
               h.z * ws[(k0 + 2) * 3 + 1] + h.w * ws[(k0 + 3) * 3 + 1];
    float s2 = h.x * ws[k0 * 3 + 2] + h.y * ws[(k0 + 1) * 3 + 2] +
               h.z * ws[(k0 + 2) * 3 + 2] + h.w * ws[(k0 + 3) * 3 + 2];
#pragma unroll
    for (int o = 16; o; o >>= 1) {
        s0 += __shfl_down_sync(0xffffffffu, s0, o);
        s1 += __shfl_down_sync(0xffffffffu, s1, o);
        s2 += __shfl_down_sync(0xffffffffu, s2, o);
    }
    if (lane == 0) {
        out[node * 3 + 0] = s0 + b2[0];
        out[node * 3 + 1] = s1 + b2[1];
        out[node * 3 + 2] = s2 + b2[2];
    }
}

// ---------------- launch ----------------
extern "C" void kernel_launch(void* const* d_in, const int* in_sizes, int n_in,
                              void* d_out, int out_size) {
    const float* z        = (const float*)d_in[0];
    const float* dist     = (const float*)d_in[1];
    const int*   ei       = (const int*)d_in[2];
    const float* init_w   = (const float*)d_in[3];
    const float* init_b   = (const float*)d_in[4];
    const float* e_lin_w[2] = {(const float*)d_in[5],  (const float*)d_in[14]};
    const float* e_m0_w[2]  = {(const float*)d_in[6],  (const float*)d_in[15]};
    const float* e_m0_b[2]  = {(const float*)d_in[7],  (const float*)d_in[16]};
    const float* e_m2_w[2]  = {(const float*)d_in[8],  (const float*)d_in[17]};
    const float* e_m2_b[2]  = {(const float*)d_in[9],  (const float*)d_in[18]};
    const float* v_l1_w[2]  = {(const float*)d_in[10], (const float*)d_in[19]};
    const float* v_l1_b[2]  = {(const float*)d_in[11], (const float*)d_in[20]};
    const float* v_l2_w[2]  = {(const float*)d_in[12], (const float*)d_in[21]};
    const float* v_l2_b[2]  = {(const float*)d_in[13], (const float*)d_in[22]};
    const float* u_l1_w   = (const float*)d_in[23];
    const float* u_l1_b   = (const float*)d_in[24];
    const float* u_l2_w   = (const float*)d_in[25];
    const float* u_l2_b   = (const float*)d_in[26];
    float* out = (float*)d_out;

    float *v, *vlin, *agg, *wtab, *cs;
    uint32_t* wpk;
    int *cnt, *off, *pos, *bsum, *jt;
    cudaGetSymbolAddress((void**)&v,    g_v);
    cudaGetSymbolAddress((void**)&vlin, g_vlin);
    cudaGetSymbolAddress((void**)&agg,  g_agg);
    cudaGetSymbolAddress((void**)&wtab, g_wtab);
    cudaGetSymbolAddress((void**)&wpk,  g_wpk);
    cudaGetSymbolAddress((void**)&cnt,  g_cnt);
    cudaGetSymbolAddress((void**)&off,  g_off);
    cudaGetSymbolAddress((void**)&pos,  g_pos);
    cudaGetSymbolAddress((void**)&bsum, g_bsum);
    cudaGetSymbolAddress((void**)&jt,   g_jt);
    cudaGetSymbolAddress((void**)&cs,   g_cs);

    cudaFuncSetAttribute((const void*)tcgemm<false, false, false>,
                         cudaFuncAttributeMaxDynamicSharedMemorySize, TCG_SMEM);
    cudaFuncSetAttribute((const void*)tcgemm<true, true, false>,
                         cudaFuncAttributeMaxDynamicSharedMemorySize, TCG_SMEM);
    cudaFuncSetAttribute((const void*)tcgemm<true, false, true>,
                         cudaFuncAttributeMaxDynamicSharedMemorySize, TCG_SMEM);

    const int egrid = (N_EDGES + 255) / 256;
    const int ngrid = (N_NODES + 255) / 256;
    const uint32_t* wm[7];  // 0:e_lin0 1:l1_0 2:l2_0 3:e_lin1 4:l1_1 5:l2_1 6:u1
    for (int i = 0; i < 7; i++) wm[i] = wpk + (size_t)i * WIMG_U32;

    table_kernel<<<2 * NBINS, H>>>(e_m0_w[0], e_m0_b[0], e_m2_w[0], e_m2_b[0],      // 0
                                   e_m0_w[1], e_m0_b[1], e_m2_w[1], e_m2_b[1], wtab);
    init_kernel<<<(N_NODES * 32 + 255) / 256, 256>>>(z, init_w, init_b, v);          // 1
    {
        dim3 wg(32, 7);
        wsplit_kernel<<<wg, 256>>>(e_lin_w[0], v_l1_w[0], v_l2_w[0],                 // 2
                                   e_lin_w[1], v_l1_w[1], v_l2_w[1], u_l1_w, wpk);
    }
    tcgemm<false, false, false><<<N_TILES, 256, TCG_SMEM>>>(                         // 3 <- profiled
        v, wm[0], nullptr, nullptr, vlin, N_NODES);
    zero_cnt_kernel<<<ngrid, 256>>>(cnt);                                            // 4
    hist_kernel<<<egrid, 256>>>(ei, cnt);                                            // 5
    scan1_kernel<<<SCAN_BLOCKS, 256>>>(cnt, off, bsum);                              // 6
    scan2_kernel<<<1, 256>>>(bsum);                                                  // 7
    scan3_kernel<<<SCAN_BLOCKS, 256>>>(off, bsum, pos);                              // 8
    scatter_kernel<<<egrid, 256>>>(ei, dist, pos, jt, cs);                           // 9

    for (int l = 0; l < 2; l++) {
        agg_kernel<<<(N_NODES + 7) / 8, 256>>>(vlin, off, jt, cs,
                                               wtab + l * NBINS * H, agg);
        // h = ssp(agg @ l1 + b1) -> vlin (consumed already)
        tcgemm<true, true, false><<<N_TILES, 256, TCG_SMEM>>>(
            agg, wm[3 * l + 1], v_l1_b[l], nullptr, vlin, N_NODES);
        // v = v + (h @ l2 + b2)
        tcgemm<true, false, true><<<N_TILES, 256, TCG_SMEM>>>(
            vlin, wm[3 * l + 2], v_l2_b[l], v, v, N_NODES);
        if (l == 0) {
            // vlin = v @ e_lin1
            tcgemm<false, false, false><<<N_TILES, 256, TCG_SMEM>>>(
                v, wm[3], nullptr, nullptr, vlin, N_NODES);
        }
    }
    // h = ssp(v @ u1 + b1) -> vlin ; out = h @ u2 + b2
    tcgemm<true, true, false><<<N_TILES, 256, TCG_SMEM>>>(
        v, wm[6], u_l1_b, nullptr, vlin, N_NODES);
    readout_kernel<<<(N_NODES * 32 + 255) / 256, 256>>>(vlin, u_l2_w, u_l2_b, out);
}

// round 9
// speedup vs baseline: 1.4820x; 1.1257x over previous
#include <cuda_runtime.h>
#include <cuda_bf16.h>
#include <mma.h>
#include <math.h>
#include <stdint.h>

using namespace nvcuda;

#define N_NODES 50000
#define N_EDGES 800000
#define H 128
#define G_RBF 50
#define NBINS 7
#define CUTOFF 6.0f
#define SSP_SHIFT 0.6931471805599453f
#define PI_F 3.14159265358979323846f

#define SCAN_BLOCKS ((N_NODES + 255) / 256)   // 196
#define TILE_M 64
#define N_TILES ((N_NODES + TILE_M - 1) / TILE_M)   // 782
#define WL 136            // bf16 leading dim (128 + 8 pad)
#define OL 132            // f32 output leading dim (128 + 4 pad)
#define WIMG_U32 17408    // per-matrix packed image: hi(8704 u32) + lo(8704 u32)

// smem layout (bytes) for tcgemm
#define SM_AHI 0
#define SM_ALO (TILE_M * WL * 2)                 // 17408
#define SM_BHI (2 * TILE_M * WL * 2)             // 34816
#define SM_BLO (SM_BHI + H * WL * 2)             // 34816 + 34816
#define TCG_SMEM (SM_BHI + 2 * H * WL * 2)       // 104448

// ---------------- scratch (no allocation allowed) ----------------
__device__ float g_v[N_NODES * H];
__device__ float g_vlin[N_NODES * H];
__device__ float g_agg[N_NODES * H];
__device__ float g_wtab[2 * NBINS * H];
__device__ uint32_t g_wpk[7 * WIMG_U32];
// CSR scratch
__device__ int   g_cnt[N_NODES];
__device__ int   g_off[N_NODES + 1];
__device__ int   g_pos[N_NODES];
__device__ int   g_bsum[SCAN_BLOCKS];
__device__ int   g_jt[N_EDGES];
__device__ float g_cs[N_EDGES];

__device__ __forceinline__ float sspf(float x) {
    return fmaxf(x, 0.0f) + log1pf(expf(-fabsf(x))) - SSP_SHIFT;
}

__device__ __forceinline__ uint32_t pack_bf16x2(float x0, float x1) {
    __nv_bfloat16 h0 = __float2bfloat16_rn(x0);
    __nv_bfloat16 h1 = __float2bfloat16_rn(x1);
    return (uint32_t)__bfloat16_as_ushort(h0) |
           ((uint32_t)__bfloat16_as_ushort(h1) << 16);
}

// ---------------- W pre-split: f32 [128,128] -> col-major bf16 hi/lo image ----------------
__global__ void wsplit_kernel(const float* __restrict__ w0, const float* __restrict__ w1,
                              const float* __restrict__ w2, const float* __restrict__ w3,
                              const float* __restrict__ w4, const float* __restrict__ w5,
                              const float* __restrict__ w6, uint32_t* __restrict__ wpk) {
    const float* ws[7] = {w0, w1, w2, w3, w4, w5, w6};
    int m = blockIdx.y;
    const float* W = ws[m];
    int t = blockIdx.x * 256 + threadIdx.x;   // 0..8191
    if (t >= 8192) return;
    int n = t & 127;          // output column
    int kp = t >> 7;          // k pair index, k = 2*kp
    float x0 = W[(2 * kp) * H + n];
    float x1 = W[(2 * kp + 1) * H + n];
    float h0 = __bfloat162float(__float2bfloat16_rn(x0));
    float h1 = __bfloat162float(__float2bfloat16_rn(x1));
    uint32_t* base = wpk + (size_t)m * WIMG_U32;
    base[(n * WL + 2 * kp) >> 1]          = pack_bf16x2(x0, x1);             // hi
    base[8704 + ((n * WL + 2 * kp) >> 1)] = pack_bf16x2(x0 - h0, x1 - h1);   // lo
}

// ---------------- tensor-core GEMM pass: out = f(A@W + b) [+res] ----------------
// 3-term bf16 split via wmma m16n16k16. 512 threads, warp tile 16x32.
template <bool BIAS, bool DOSSP, bool RES>
__global__ void __launch_bounds__(512, 2) tcgemm(const float* __restrict__ A,
                                                 const uint32_t* __restrict__ wpk,
                                                 const float* __restrict__ bias,
                                                 const float* __restrict__ res,
                                                 float* __restrict__ out, int n) {
    extern __shared__ char sm[];
    __shared__ float bsm[H];
    int tid = threadIdx.x;
    int nb = blockIdx.x * TILE_M;

    if (BIAS && tid < H) bsm[tid] = bias[tid];

    // stage B (pre-split, pre-laid-out): one contiguous 69632-byte copy
    {
        const float4* src = (const float4*)wpk;
        float4* dst = (float4*)(sm + SM_BHI);
        for (int i = tid; i < (2 * H * WL * 2) / 16; i += 512) dst[i] = src[i];
    }
    // stage A: split f32 -> bf16 hi/lo, row-major ldm WL
    for (int idx = tid; idx < TILE_M * 32; idx += 512) {
        int node = idx >> 5, c = idx & 31;    // k = 4c
        int gn = nb + node;
        float4 a = (gn < n) ? ((const float4*)A)[(size_t)gn * 32 + c]
                            : make_float4(0.f, 0.f, 0.f, 0.f);
        float hx = __bfloat162float(__float2bfloat16_rn(a.x));
        float hy = __bfloat162float(__float2bfloat16_rn(a.y));
        float hz = __bfloat162float(__float2bfloat16_rn(a.z));
        float hw = __bfloat162float(__float2bfloat16_rn(a.w));
        uint32_t hlo = pack_bf16x2(a.x, a.y), hhi = pack_bf16x2(a.z, a.w);
        uint32_t llo = pack_bf16x2(a.x - hx, a.y - hy), lhi = pack_bf16x2(a.z - hz, a.w - hw);
        uint32_t boff = 2 * (node * WL + 4 * c);   // 8-byte aligned
        *(uint2*)(sm + SM_AHI + boff) = make_uint2(hlo, hhi);
        *(uint2*)(sm + SM_ALO + boff) = make_uint2(llo, lhi);
    }
    __syncthreads();

    int wid = tid >> 5;
    int wrow = wid & 3;          // node group (16 nodes)
    int wcol = wid >> 2;         // 32-col group (0..3)

    const __nv_bfloat16* Ahi = (const __nv_bfloat16*)(sm + SM_AHI) + wrow * 16 * WL;
    const __nv_bfloat16* Alo = (const __nv_bfloat16*)(sm + SM_ALO) + wrow * 16 * WL;
    const __nv_bfloat16* Bhi = (const __nv_bfloat16*)(sm + SM_BHI);
    const __nv_bfloat16* Blo = (const __nv_bfloat16*)(sm + SM_BLO);

    wmma::fragment<wmma::accumulator, 16, 16, 16, float> acc[2];
#pragma unroll
    for (int t = 0; t < 2; t++) wmma::fill_fragment(acc[t], 0.0f);

#pragma unroll
    for (int ks = 0; ks < 8; ks++) {
        wmma::fragment<wmma::matrix_a, 16, 16, 16, __nv_bfloat16, wmma::row_major> ah, al;
        wmma::load_matrix_sync(ah, Ahi + ks * 16, WL);
        wmma::load_matrix_sync(al, Alo + ks * 16, WL);
#pragma unroll
        for (int t = 0; t < 2; t++) {
            int ncol = wcol * 32 + t * 16;
            wmma::fragment<wmma::matrix_b, 16, 16, 16, __nv_bfloat16, wmma::col_major> bh, bl;
            wmma::load_matrix_sync(bh, Bhi + ncol * WL + ks * 16, WL);
            wmma::load_matrix_sync(bl, Blo + ncol * WL + ks * 16, WL);
            wmma::mma_sync(acc[t], ah, bh, acc[t]);
            wmma::mma_sync(acc[t], ah, bl, acc[t]);
            wmma::mma_sync(acc[t], al, bh, acc[t]);
        }
    }

    __syncthreads();   // all warps done reading A/B; overlay output on A region
    float* osm = (float*)(sm + SM_AHI);
#pragma unroll
    for (int t = 0; t < 2; t++)
        wmma::store_matrix_sync(osm + wrow * 16 * OL + wcol * 32 + t * 16,
                                acc[t], OL, wmma::mem_row_major);
    __syncthreads();

    // epilogue: thread -> (node = tid/8, 16-col group = (tid&7)*16)
    {
        int node = tid >> 3;
        int cb = (tid & 7) * 16;
        int gn = nb + node;
        if (gn < n) {
            const float* ip = osm + node * OL + cb;
            float* op = out + (size_t)gn * H + cb;
            const float4* rp = RES ? (const float4*)(res + (size_t)gn * H + cb) : nullptr;
#pragma unroll
            for (int i = 0; i < 4; i++) {
                float4 o;
                o.x = ip[4 * i + 0]; o.y = ip[4 * i + 1];
                o.z = ip[4 * i + 2]; o.w = ip[4 * i + 3];
                if (BIAS) {
                    o.x += bsm[cb + 4 * i + 0]; o.y += bsm[cb + 4 * i + 1];
                    o.z += bsm[cb + 4 * i + 2]; o.w += bsm[cb + 4 * i + 3];
                }
                if (DOSSP) { o.x = sspf(o.x); o.y = sspf(o.y); o.z = sspf(o.z); o.w = sspf(o.w); }
                if (RES) {
                    float4 r = rp[i];
                    o.x += r.x; o.y += r.y; o.z += r.z; o.w += r.w;
                }
                ((float4*)op)[i] = o;
            }
        }
    }
}

// ---------------- filter table ----------------
__global__ void table_kernel(const float* __restrict__ m0w0, const float* __restrict__ m0b0,
                             const float* __restrict__ m2w0, const float* __restrict__ m2b0,
                             const float* __restrict__ m0w1, const float* __restrict__ m0b1,
                             const float* __restrict__ m2w1, const float* __restrict__ m2b1,
                             float* __restrict__ wtab) {
    int l = blockIdx.x / NBINS;
    int t = blockIdx.x % NBINS;
    const float* m0w = l ? m0w1 : m0w0;
    const float* m0b = l ? m0b1 : m0b0;
    const float* m2w = l ? m2w1 : m2w0;
    const float* m2b = l ? m2b1 : m2b0;
    __shared__ float hs[H];
    int h = threadIdx.x;
    const float step = CUTOFF / (float)(G_RBF - 1);
    const float coeff = -0.5f / (step * step);
    float acc = m0b[h];
#pragma unroll 10
    for (int g = 0; g < G_RBF; g++) {
        float dd = (float)t - step * (float)g;
        acc += expf(coeff * dd * dd) * m0w[g * H + h];
    }
    hs[h] = sspf(acc);
    __syncthreads();
    float o = m2b[h];
#pragma unroll 16
    for (int k = 0; k < H; k++) o += hs[k] * m2w[k * H + h];
    wtab[(l * NBINS + t) * H + h] = o;
}

// ---------------- init: v = z @ init_w + init_b ----------------
__global__ void init_kernel(const float* __restrict__ z, const float* __restrict__ iw,
                            const float* __restrict__ ib, float* __restrict__ v) {
    int g = blockIdx.x * blockDim.x + threadIdx.x;
    if (g >= N_NODES * 32) return;
    int nn = g >> 5, c4 = g & 31;
    float4 b = ((const float4*)ib)[c4];
    float z0 = z[nn * 3 + 0], z1 = z[nn * 3 + 1], z2 = z[nn * 3 + 2];
    float4 w0 = ((const float4*)iw)[c4];
    float4 w1 = ((const float4*)iw)[32 + c4];
    float4 w2 = ((const float4*)iw)[64 + c4];
    float4 o;
    o.x = b.x + z0 * w0.x + z1 * w1.x + z2 * w2.x;
    o.y = b.y + z0 * w0.y + z1 * w1.y + z2 * w2.y;
    o.z = b.z + z0 * w0.z + z1 * w1.z + z2 * w2.z;
    o.w = b.w + z0 * w0.w + z1 * w1.w + z2 * w2.w;
    ((float4*)v)[nn * 32 + c4] = o;
}

// ---------------- CSR build ----------------
__global__ void zero_cnt_kernel(int* __restrict__ cnt) {
    int i = blockIdx.x * blockDim.x + threadIdx.x;
    if (i < N_NODES) cnt[i] = 0;
}
__global__ void hist_kernel(const int* __restrict__ ei, int* __restrict__ cnt) {
    int e = blockIdx.x * blockDim.x + threadIdx.x;
    if (e < N_EDGES) atomicAdd(&cnt[ei[N_EDGES + e]], 1);
}
__global__ void scan1_kernel(const int* __restrict__ cnt, int* __restrict__ off,
                             int* __restrict__ bsum) {
    __shared__ int s[256];
    int t = threadIdx.x;
    int i = blockIdx.x * 256 + t;
    int v = (i < N_NODES) ? cnt[i] : 0;
    s[t] = v;
    __syncthreads();
#pragma unroll
    for (int o = 1; o < 256; o <<= 1) {
        int x = (t >= o) ? s[t - o] : 0;
        __syncthreads();
        s[t] += x;
        __syncthreads();
    }
    if (i < N_NODES) off[i] = s[t] - v;
    if (t == 255) bsum[blockIdx.x] = s[255];
}
__global__ void scan2_kernel(int* __restrict__ bsum) {
    __shared__ int s[256];
    int t = threadIdx.x;
    int v = (t < SCAN_BLOCKS) ? bsum[t] : 0;
    s[t] = v;
    __syncthreads();
#pragma unroll
    for (int o = 1; o < 256; o <<= 1) {
        int x = (t >= o) ? s[t - o] : 0;
        __syncthreads();
        s[t] += x;
        __syncthreads();
    }
    if (t < SCAN_BLOCKS) bsum[t] = s[t] - v;
}
__global__ void scan3_kernel(int* __restrict__ off, const int* __restrict__ bsum,
                             int* __restrict__ pos) {
    int i = blockIdx.x * blockDim.x + threadIdx.x;
    if (i < N_NODES) {
        int o = off[i] + bsum[i >> 8];
        off[i] = o;
        pos[i] = o;
    }
    if (i == 0) off[N_NODES] = N_EDGES;
}
__global__ void scatter_kernel(const int* __restrict__ ei, const float* __restrict__ dist,
                               int* __restrict__ pos, int* __restrict__ jt,
                               float* __restrict__ cs) {
    int e = blockIdx.x * blockDim.x + threadIdx.x;
    if (e >= N_EDGES) return;
    int j = ei[e];
    int i = ei[N_EDGES + e];
    float d = dist[e];
    int tb = (int)d;
    if (tb > NBINS - 1) tb = NBINS - 1;
    float C = 0.5f * cosf(d * (PI_F / CUTOFF)) + 0.5f;
    int p = atomicAdd(&pos[i], 1);
    jt[p] = j | (tb << 27);
    cs[p] = C;
}

// ---------------- aggregate ----------------
__global__ void __launch_bounds__(256) agg_kernel(const float* __restrict__ vlin,
                                                  const int* __restrict__ off,
                                                  const int* __restrict__ jt,
                                                  const float* __restrict__ cs,
                                                  const float* __restrict__ wtab,
                                                  float* __restrict__ agg) {
    __shared__ float4 ws[NBINS * 32];
    int tid = threadIdx.x;
    if (tid < NBINS * 32) ws[tid] = ((const float4*)wtab)[tid];
    __syncthreads();

    int node = blockIdx.x * 8 + (tid >> 5);
    if (node >= N_NODES) return;
    int lane = tid & 31;
    int s = off[node], e = off[node + 1];
    float4 acc = make_float4(0.f, 0.f, 0.f, 0.f);
    const float4* vlin4 = (const float4*)vlin;

    for (int base = s; base < e; base += 32) {
        int m = min(32, e - base);
        int mj = (lane < m) ? jt[base + lane] : 0;
        float mc = (lane < m) ? cs[base + lane] : 0.f;
        int t = 0;
        for (; t + 4 <= m; t += 4) {
            int jv0 = __shfl_sync(0xffffffffu, mj, t);
            int jv1 = __shfl_sync(0xffffffffu, mj, t + 1);
            int jv2 = __shfl_sync(0xffffffffu, mj, t + 2);
            int jv3 = __shfl_sync(0xffffffffu, mj, t + 3);
            float c0 = __shfl_sync(0xffffffffu, mc, t);
            float c1 = __shfl_sync(0xffffffffu, mc, t + 1);
            float c2 = __shfl_sync(0xffffffffu, mc, t + 2);
            float c3 = __shfl_sync(0xffffffffu, mc, t + 3);
            float4 x0 = __ldg(vlin4 + (size_t)(jv0 & 0x07FFFFFF) * 32 + lane);
            float4 x1 = __ldg(vlin4 + (size_t)(jv1 & 0x07FFFFFF) * 32 + lane);
            float4 x2 = __ldg(vlin4 + (size_t)(jv2 & 0x07FFFFFF) * 32 + lane);
            float4 x3 = __ldg(vlin4 + (size_t)(jv3 & 0x07FFFFFF) * 32 + lane);
            float4 w0 = ws[(jv0 >> 27) * 32 + lane];
            float4 w1 = ws[(jv1 >> 27) * 32 + lane];
            float4 w2 = ws[(jv2 >> 27) * 32 + lane];
            float4 w3 = ws[(jv3 >> 27) * 32 + lane];
            acc.x += x0.x * w0.x * c0; acc.y += x0.y * w0.y * c0;
            acc.z += x0.z * w0.z * c0; acc.w += x0.w * w0.w * c0;
            acc.x += x1.x * w1.x * c1; acc.y += x1.y * w1.y * c1;
            acc.z += x1.z * w1.z * c1; acc.w += x1.w * w1.w * c1;
            acc.x += x2.x * w2.x * c2; acc.y += x2.y * w2.y * c2;
            acc.z += x2.z * w2.z * c2; acc.w += x2.w * w2.w * c2;
            acc.x += x3.x * w3.x * c3; acc.y += x3.y * w3.y * c3;
            acc.z += x3.z * w3.z * c3; acc.w += x3.w * w3.w * c3;
        }
        for (; t < m; t++) {
            int jv = __shfl_sync(0xffffffffu, mj, t);
            float c = __shfl_sync(0xffffffffu, mc, t);
            float4 x = __ldg(vlin4 + (size_t)(jv & 0x07FFFFFF) * 32 + lane);
            float4 w = ws[(jv >> 27) * 32 + lane];
            acc.x += x.x * w.x * c;
            acc.y += x.y * w.y * c;
            acc.z += x.z * w.z * c;
            acc.w += x.w * w.w * c;
        }
    }
    ((float4*)agg)[(size_t)node * 32 + lane] = acc;
}

// ---------------- readout: out = h @ u2 + b2 ----------------
__global__ void __launch_bounds__(256) readout_kernel(const float* __restrict__ hbuf,
                                                      const float* __restrict__ w2,
                                                      const float* __restrict__ b2,
                                                      float* __restrict__ out) {
    __shared__ float ws[H * 3];
    int tid = threadIdx.x;
    for (int idx = tid; idx < H * 3; idx += 256) ws[idx] = w2[idx];
    __syncthreads();

    int g = blockIdx.x * 256 + tid;
    int node = g >> 5;
    if (node >= N_NODES) return;
    int lane = g & 31;
    float4 h = ((const float4*)hbuf)[node * 32 + lane];
    int k0 = lane * 4;
    float s0 = h.x * ws[k0 * 3 + 0] + h.y * ws[(k0 + 1) * 3 + 0] +
               h.z * ws[(k0 + 2) * 3 + 0] + h.w * ws[(k0 + 3) * 3 + 0];
    float s1 = h.x * ws[k0 * 3 + 1] + h.y * ws[(k0 + 1) * 3 + 1] +
               h.z * ws[(k0 + 2) * 3 + 1] + h.w * ws[(k0 + 3) * 3 + 1];
    float s2 = h.x * ws[k0 * 3 + 2] + h.y * ws[(k0 + 1) * 3 + 2] +
               h.z * ws[(k0 + 2) * 3 + 2] + h.w * ws[(k0 + 3) * 3 + 2];
#pragma unroll
    for (int o = 16; o; o >>= 1) {
        s0 += __shfl_down_sync(0xffffffffu, s0, o);
        s1 += __shfl_down_sync(0xffffffffu, s1, o);
        s2 += __shfl_down_sync(0xffffffffu, s2, o);
    }
    if (lane == 0) {
        out[node * 3 + 0] = s0 + b2[0];
        out[node * 3 + 1] = s1 + b2[1];
        out[node * 3 + 2] = s2 + b2[2];
    }
}

// ---------------- launch ----------------
extern "C" void kernel_launch(void* const* d_in, const int* in_sizes, int n_in,
                              void* d_out, int out_size) {
    const float* z        = (const float*)d_in[0];
    const float* dist     = (const float*)d_in[1];
    const int*   ei       = (const int*)d_in[2];
    const float* init_w   = (const float*)d_in[3];
    const float* init_b   = (const float*)d_in[4];
    const float* e_lin_w[2] = {(const float*)d_in[5],  (const float*)d_in[14]};
    const float* e_m0_w[2]  = {(const float*)d_in[6],  (const float*)d_in[15]};
    const float* e_m0_b[2]  = {(const float*)d_in[7],  (const float*)d_in[16]};
    const float* e_m2_w[2]  = {(const float*)d_in[8],  (const float*)d_in[17]};
    const float* e_m2_b[2]  = {(const float*)d_in[9],  (const float*)d_in[18]};
    const float* v_l1_w[2]  = {(const float*)d_in[10], (const float*)d_in[19]};
    const float* v_l1_b[2]  = {(const float*)d_in[11], (const float*)d_in[20]};
    const float* v_l2_w[2]  = {(const float*)d_in[12], (const float*)d_in[21]};
    const float* v_l2_b[2]  = {(const float*)d_in[13], (const float*)d_in[22]};
    const float* u_l1_w   = (const float*)d_in[23];
    const float* u_l1_b   = (const float*)d_in[24];
    const float* u_l2_w   = (const float*)d_in[25];
    const float* u_l2_b   = (const float*)d_in[26];
    float* out = (float*)d_out;

    float *v, *vlin, *agg, *wtab, *cs;
    uint32_t* wpk;
    int *cnt, *off, *pos, *bsum, *jt;
    cudaGetSymbolAddress((void**)&v,    g_v);
    cudaGetSymbolAddress((void**)&vlin, g_vlin);
    cudaGetSymbolAddress((void**)&agg,  g_agg);
    cudaGetSymbolAddress((void**)&wtab, g_wtab);
    cudaGetSymbolAddress((void**)&wpk,  g_wpk);
    cudaGetSymbolAddress((void**)&cnt,  g_cnt);
    cudaGetSymbolAddress((void**)&off,  g_off);
    cudaGetSymbolAddress((void**)&pos,  g_pos);
    cudaGetSymbolAddress((void**)&bsum, g_bsum);
    cudaGetSymbolAddress((void**)&jt,   g_jt);
    cudaGetSymbolAddress((void**)&cs,   g_cs);

    cudaFuncSetAttribute((const void*)tcgemm<false, false, false>,
                         cudaFuncAttributeMaxDynamicSharedMemorySize, TCG_SMEM);
    cudaFuncSetAttribute((const void*)tcgemm<true, true, false>,
                         cudaFuncAttributeMaxDynamicSharedMemorySize, TCG_SMEM);
    cudaFuncSetAttribute((const void*)tcgemm<true, false, true>,
                         cudaFuncAttributeMaxDynamicSharedMemorySize, TCG_SMEM);

    const int egrid = (N_EDGES + 255) / 256;
    const int ngrid = (N_NODES + 255) / 256;
    const uint32_t* wm[7];  // 0:e_lin0 1:l1_0 2:l2_0 3:e_lin1 4:l1_1 5:l2_1 6:u1
    for (int i = 0; i < 7; i++) wm[i] = wpk + (size_t)i * WIMG_U32;

    table_kernel<<<2 * NBINS, H>>>(e_m0_w[0], e_m0_b[0], e_m2_w[0], e_m2_b[0],      // 0
                                   e_m0_w[1], e_m0_b[1], e_m2_w[1], e_m2_b[1], wtab);
    init_kernel<<<(N_NODES * 32 + 255) / 256, 256>>>(z, init_w, init_b, v);          // 1
    {
        dim3 wg(32, 7);
        wsplit_kernel<<<wg, 256>>>(e_lin_w[0], v_l1_w[0], v_l2_w[0],                 // 2
                                   e_lin_w[1], v_l1_w[1], v_l2_w[1], u_l1_w, wpk);
    }
    tcgemm<false, false, false><<<N_TILES, 512, TCG_SMEM>>>(                         // 3 <- profiled
        v, wm[0], nullptr, nullptr, vlin, N_NODES);
    zero_cnt_kernel<<<ngrid, 256>>>(cnt);                                            // 4
    hist_kernel<<<egrid, 256>>>(ei, cnt);                                            // 5
    scan1_kernel<<<SCAN_BLOCKS, 256>>>(cnt, off, bsum);                              // 6
    scan2_kernel<<<1, 256>>>(bsum);                                                  // 7
    scan3_kernel<<<SCAN_BLOCKS, 256>>>(off, bsum, pos);                              // 8
    scatter_kernel<<<egrid, 256>>>(ei, dist, pos, jt, cs);                           // 9

    for (int l = 0; l < 2; l++) {
        agg_kernel<<<(N_NODES + 7) / 8, 256>>>(vlin, off, jt, cs,
                                               wtab + l * NBINS * H, agg);
        // h = ssp(agg @ l1 + b1) -> vlin (consumed already)
        tcgemm<true, true, false><<<N_TILES, 512, TCG_SMEM>>>(
            agg, wm[3 * l + 1], v_l1_b[l], nullptr, vlin, N_NODES);
        // v = v + (h @ l2 + b2)
        tcgemm<true, false, true><<<N_TILES, 512, TCG_SMEM>>>(
            vlin, wm[3 * l + 2], v_l2_b[l], v, v, N_NODES);
        if (l == 0) {
            // vlin = v @ e_lin1
            tcgemm<false, false, false><<<N_TILES, 512, TCG_SMEM>>>(
                v, wm[3], nullptr, nullptr, vlin, N_NODES);
        }
    }
    // h = ssp(v @ u1 + b1) -> vlin ; out = h @ u2 + b2
    tcgemm<true, true, false><<<N_TILES, 512, TCG_SMEM>>>(
        v, wm[6], u_l1_b, nullptr, vlin, N_NODES);
    readout_kernel<<<(N_NODES * 32 + 255) / 256, 256>>>(vlin, u_l2_w, u_l2_b, out);
}

// round 10
// speedup vs baseline: 1.5942x; 1.0757x over previous
#include <cuda_runtime.h>
#include <cuda_bf16.h>
#include <mma.h>
#include <math.h>
#include <stdint.h>

using namespace nvcuda;

#define N_NODES 50000
#define N_EDGES 800000
#define H 128
#define G_RBF 50
#define NBINS 7
#define CUTOFF 6.0f
#define SSP_SHIFT 0.6931471805599453f
#define PI_F 3.14159265358979323846f

#define SCAN_BLOCKS ((N_NODES + 255) / 256)   // 196
#define TILE_M 64
#define N_TILES ((N_NODES + TILE_M - 1) / TILE_M)   // 782
#define WL 136            // bf16 leading dim (128 + 8 pad)
#define OL 132            // f32 output leading dim (128 + 4 pad)
#define WIMG_U32 17408    // per-matrix packed image: hi(8704 u32) + lo(8704 u32)

// smem layout (bytes)
#define SM_AHI 0
#define SM_ALO (TILE_M * WL * 2)                 // 17408
#define SM_BHI (2 * TILE_M * WL * 2)             // 34816
#define SM_BLO (SM_BHI + H * WL * 2)
#define TCG_SMEM (SM_BHI + 2 * H * WL * 2)       // 104448

// ---------------- scratch ----------------
__device__ float g_v[N_NODES * H];
__device__ float g_vlin[N_NODES * H];
__device__ float g_agg[N_NODES * H];
__device__ float g_wtab[2 * NBINS * H];
__device__ uint32_t g_wpk[7 * WIMG_U32];
__device__ int   g_cnt[N_NODES];
__device__ int   g_off[N_NODES + 1];
__device__ int   g_pos[N_NODES];
__device__ int   g_bsum[SCAN_BLOCKS];
__device__ int   g_jt[N_EDGES];
__device__ float g_cs[N_EDGES];

__device__ __forceinline__ float sspf(float x) {
    return fmaxf(x, 0.0f) + log1pf(expf(-fabsf(x))) - SSP_SHIFT;
}

__device__ __forceinline__ uint32_t pack_bf16x2(float x0, float x1) {
    __nv_bfloat16 h0 = __float2bfloat16_rn(x0);
    __nv_bfloat16 h1 = __float2bfloat16_rn(x1);
    return (uint32_t)__bfloat16_as_ushort(h0) |
           ((uint32_t)__bfloat16_as_ushort(h1) << 16);
}

// ---------------- W pre-split ----------------
__global__ void wsplit_kernel(const float* __restrict__ w0, const float* __restrict__ w1,
                              const float* __restrict__ w2, const float* __restrict__ w3,
                              const float* __restrict__ w4, const float* __restrict__ w5,
                              const float* __restrict__ w6, uint32_t* __restrict__ wpk) {
    const float* ws[7] = {w0, w1, w2, w3, w4, w5, w6};
    int m = blockIdx.y;
    const float* W = ws[m];
    int t = blockIdx.x * 256 + threadIdx.x;
    if (t >= 8192) return;
    int n = t & 127;
    int kp = t >> 7;
    float x0 = W[(2 * kp) * H + n];
    float x1 = W[(2 * kp + 1) * H + n];
    float h0 = __bfloat162float(__float2bfloat16_rn(x0));
    float h1 = __bfloat162float(__float2bfloat16_rn(x1));
    uint32_t* base = wpk + (size_t)m * WIMG_U32;
    base[(n * WL + 2 * kp) >> 1]          = pack_bf16x2(x0, x1);
    base[8704 + ((n * WL + 2 * kp) >> 1)] = pack_bf16x2(x0 - h0, x1 - h1);
}

// ================= shared building blocks for tensor kernels =================
// stage B image (70KB contiguous) into smem
__device__ __forceinline__ void stage_B(char* sm, const uint32_t* wpk, int tid) {
    const float4* src = (const float4*)wpk;
    float4* dst = (float4*)(sm + SM_BHI);
    for (int i = tid; i < (2 * H * WL * 2) / 16; i += 512) dst[i] = src[i];
}

// split one float4 (4 consecutive k of one node) into hi/lo bf16 and store
__device__ __forceinline__ void store_A4(char* sm, int node, int c, float4 a) {
    float hx = __bfloat162float(__float2bfloat16_rn(a.x));
    float hy = __bfloat162float(__float2bfloat16_rn(a.y));
    float hz = __bfloat162float(__float2bfloat16_rn(a.z));
    float hw = __bfloat162float(__float2bfloat16_rn(a.w));
    uint32_t boff = 2 * (node * WL + 4 * c);
    *(uint2*)(sm + SM_AHI + boff) = make_uint2(pack_bf16x2(a.x, a.y), pack_bf16x2(a.z, a.w));
    *(uint2*)(sm + SM_ALO + boff) = make_uint2(pack_bf16x2(a.x - hx, a.y - hy),
                                               pack_bf16x2(a.z - hz, a.w - hw));
}

// 3-term bf16-split MMA set over the staged tiles; acc[2] per warp (16x32 tile)
__device__ __forceinline__ void mma_set(const char* sm, int wid,
        wmma::fragment<wmma::accumulator, 16, 16, 16, float>* acc) {
    int wrow = wid & 3, wcol = wid >> 2;
    const __nv_bfloat16* Ahi = (const __nv_bfloat16*)(sm + SM_AHI) + wrow * 16 * WL;
    const __nv_bfloat16* Alo = (const __nv_bfloat16*)(sm + SM_ALO) + wrow * 16 * WL;
    const __nv_bfloat16* Bhi = (const __nv_bfloat16*)(sm + SM_BHI);
    const __nv_bfloat16* Blo = (const __nv_bfloat16*)(sm + SM_BLO);
#pragma unroll
    for (int t = 0; t < 2; t++) wmma::fill_fragment(acc[t], 0.0f);
#pragma unroll
    for (int ks = 0; ks < 8; ks++) {
        wmma::fragment<wmma::matrix_a, 16, 16, 16, __nv_bfloat16, wmma::row_major> ah, al;
        wmma::load_matrix_sync(ah, Ahi + ks * 16, WL);
        wmma::load_matrix_sync(al, Alo + ks * 16, WL);
#pragma unroll
        for (int t = 0; t < 2; t++) {
            int ncol = wcol * 32 + t * 16;
            wmma::fragment<wmma::matrix_b, 16, 16, 16, __nv_bfloat16, wmma::col_major> bh, bl;
            wmma::load_matrix_sync(bh, Bhi + ncol * WL + ks * 16, WL);
            wmma::load_matrix_sync(bl, Blo + ncol * WL + ks * 16, WL);
            wmma::mma_sync(acc[t], ah, bh, acc[t]);
            wmma::mma_sync(acc[t], ah, bl, acc[t]);
            wmma::mma_sync(acc[t], al, bh, acc[t]);
        }
    }
}

// store acc set to osm (overlay on A region). Caller syncs before+after.
__device__ __forceinline__ void store_set(char* sm, int wid,
        wmma::fragment<wmma::accumulator, 16, 16, 16, float>* acc) {
    int wrow = wid & 3, wcol = wid >> 2;
    float* osm = (float*)(sm + SM_AHI);
#pragma unroll
    for (int t = 0; t < 2; t++)
        wmma::store_matrix_sync(osm + wrow * 16 * OL + wcol * 32 + t * 16,
                                acc[t], OL, wmma::mem_row_major);
}

// ---------------- gemm0_fused: v = z@iw+ib (written), vlin = v @ e_lin0 ----------------
__global__ void __launch_bounds__(512, 2) gemm0_fused(const float* __restrict__ z,
                                                      const float* __restrict__ iw,
                                                      const float* __restrict__ ib,
                                                      const uint32_t* __restrict__ wpk,
                                                      float* __restrict__ vout,
                                                      float* __restrict__ vlin, int n) {
    extern __shared__ char sm[];
    int tid = threadIdx.x;
    int nb = blockIdx.x * TILE_M;

    stage_B(sm, wpk, tid);
    for (int idx = tid; idx < TILE_M * 32; idx += 512) {
        int node = idx >> 5, c = idx & 31;
        int gn = nb + node;
        float4 val = make_float4(0.f, 0.f, 0.f, 0.f);
        if (gn < n) {
            float z0 = __ldg(z + gn * 3), z1 = __ldg(z + gn * 3 + 1), z2 = __ldg(z + gn * 3 + 2);
            float4 b  = __ldg((const float4*)ib + c);
            float4 w0 = __ldg((const float4*)iw + c);
            float4 w1 = __ldg((const float4*)iw + 32 + c);
            float4 w2 = __ldg((const float4*)iw + 64 + c);
            val.x = b.x + z0 * w0.x + z1 * w1.x + z2 * w2.x;
            val.y = b.y + z0 * w0.y + z1 * w1.y + z2 * w2.y;
            val.z = b.z + z0 * w0.z + z1 * w1.z + z2 * w2.z;
            val.w = b.w + z0 * w0.w + z1 * w1.w + z2 * w2.w;
            ((float4*)vout)[(size_t)gn * 32 + c] = val;
        }
        store_A4(sm, node, c, val);
    }
    __syncthreads();

    int wid = tid >> 5;
    wmma::fragment<wmma::accumulator, 16, 16, 16, float> acc[2];
    mma_set(sm, wid, acc);
    __syncthreads();
    store_set(sm, wid, acc);
    __syncthreads();

    int node = tid >> 3, cb = (tid & 7) * 16;
    int gn = nb + node;
    if (gn < n) {
        const float* ip = (const float*)(sm + SM_AHI) + node * OL + cb;
        float4* op = (float4*)(vlin + (size_t)gn * H + cb);
#pragma unroll
        for (int i = 0; i < 4; i++)
            op[i] = make_float4(ip[4 * i], ip[4 * i + 1], ip[4 * i + 2], ip[4 * i + 3]);
    }
}

// ---------------- mlp_fused: v += ssp(agg@W1+b1)@W2 + b2 ; opt vlin = v@linW ----------------
template <bool MAKE_VLIN>
__global__ void __launch_bounds__(512, 2) mlp_fused(const float* __restrict__ A,
                                                    const uint32_t* __restrict__ wpk1,
                                                    const float* __restrict__ b1,
                                                    const uint32_t* __restrict__ wpk2,
                                                    const float* __restrict__ b2,
                                                    float* __restrict__ v,
                                                    const uint32_t* __restrict__ wpkL,
                                                    float* __restrict__ vlin, int n) {
    extern __shared__ char sm[];
    __shared__ float bs1[H], bs2[H];
    int tid = threadIdx.x;
    int nb = blockIdx.x * TILE_M;
    if (tid < H) { bs1[tid] = b1[tid]; bs2[tid] = b2[tid]; }

    stage_B(sm, wpk1, tid);
    for (int idx = tid; idx < TILE_M * 32; idx += 512) {
        int node = idx >> 5, c = idx & 31;
        int gn = nb + node;
        float4 val = (gn < n) ? ((const float4*)A)[(size_t)gn * 32 + c]
                              : make_float4(0.f, 0.f, 0.f, 0.f);
        store_A4(sm, node, c, val);
    }
    __syncthreads();

    int wid = tid >> 5;
    int node = tid >> 3, cb = (tid & 7) * 16;
    int gn = nb + node;
    wmma::fragment<wmma::accumulator, 16, 16, 16, float> acc[2];

    // ---- set 1: h = ssp(agg@W1 + b1) ----
    mma_set(sm, wid, acc);
    __syncthreads();
    store_set(sm, wid, acc);
    __syncthreads();

    float t1[16];
    {
        const float* ip = (const float*)(sm + SM_AHI) + node * OL + cb;
#pragma unroll
        for (int i = 0; i < 16; i++) t1[i] = sspf(ip[i] + bs1[cb + i]);
    }
    __syncthreads();   // all osm reads done before A-region rewrite
#pragma unroll
    for (int i = 0; i < 4; i++)
        store_A4(sm, node, (cb >> 2) + i,
                 make_float4(t1[4 * i], t1[4 * i + 1], t1[4 * i + 2], t1[4 * i + 3]));
    stage_B(sm, wpk2, tid);
    __syncthreads();

    // ---- set 2: o = h@W2 + b2 + v ----
    mma_set(sm, wid, acc);
    __syncthreads();
    store_set(sm, wid, acc);
    __syncthreads();

    float o[16];
    {
        const float* ip = (const float*)(sm + SM_AHI) + node * OL + cb;
        if (gn < n) {
            const float* rp = v + (size_t)gn * H + cb;
#pragma unroll
            for (int i = 0; i < 16; i++) o[i] = ip[i] + bs2[cb + i] + rp[i];
            float4* op = (float4*)(v + (size_t)gn * H + cb);
#pragma unroll
            for (int i = 0; i < 4; i++)
                op[i] = make_float4(o[4 * i], o[4 * i + 1], o[4 * i + 2], o[4 * i + 3]);
        } else {
#pragma unroll
            for (int i = 0; i < 16; i++) o[i] = 0.f;
        }
    }

    if (MAKE_VLIN) {
        __syncthreads();   // osm reads done
#pragma unroll
        for (int i = 0; i < 4; i++)
            store_A4(sm, node, (cb >> 2) + i,
                     make_float4(o[4 * i], o[4 * i + 1], o[4 * i + 2], o[4 * i + 3]));
        stage_B(sm, wpkL, tid);
        __syncthreads();

        // ---- set 3: vlin = v_new @ linW ----
        mma_set(sm, wid, acc);
        __syncthreads();
        store_set(sm, wid, acc);
        __syncthreads();

        if (gn < n) {
            const float* ip = (const float*)(sm + SM_AHI) + node * OL + cb;
            float4* op = (float4*)(vlin + (size_t)gn * H + cb);
#pragma unroll
            for (int i = 0; i < 4; i++)
                op[i] = make_float4(ip[4 * i], ip[4 * i + 1], ip[4 * i + 2], ip[4 * i + 3]);
        }
    }
}

// ---------------- readout_fused: out = ssp(v@u1+b1) @ u2 + b2  ([N,3]) ----------------
__global__ void __launch_bounds__(512, 2) readout_fused(const float* __restrict__ A,
                                                        const uint32_t* __restrict__ wpk1,
                                                        const float* __restrict__ b1,
                                                        const float* __restrict__ W2,
                                                        const float* __restrict__ b2,
                                                        float* __restrict__ out, int n) {
    extern __shared__ char sm[];
    __shared__ float bs1[H], ws2[H * 3];
    int tid = threadIdx.x;
    int nb = blockIdx.x * TILE_M;
    if (tid < H) bs1[tid] = b1[tid];
    for (int idx = tid; idx < H * 3; idx += 512) ws2[idx] = W2[idx];

    stage_B(sm, wpk1, tid);
    for (int idx = tid; idx < TILE_M * 32; idx += 512) {
        int node = idx >> 5, c = idx & 31;
        int gn = nb + node;
        float4 val = (gn < n) ? ((const float4*)A)[(size_t)gn * 32 + c]
                              : make_float4(0.f, 0.f, 0.f, 0.f);
        store_A4(sm, node, c, val);
    }
    __syncthreads();

    int wid = tid >> 5;
    wmma::fragment<wmma::accumulator, 16, 16, 16, float> acc[2];
    mma_set(sm, wid, acc);
    __syncthreads();
    store_set(sm, wid, acc);
    __syncthreads();

    int node = tid >> 3, cb = (tid & 7) * 16;
    int gn = nb + node;
    float p0 = 0.f, p1 = 0.f, p2 = 0.f;
    {
        const float* ip = (const float*)(sm + SM_AHI) + node * OL + cb;
#pragma unroll
        for (int i = 0; i < 16; i++) {
            float x = sspf(ip[i] + bs1[cb + i]);
            int col = cb + i;
            p0 += x * ws2[col * 3 + 0];
            p1 += x * ws2[col * 3 + 1];
            p2 += x * ws2[col * 3 + 2];
        }
    }
#pragma unroll
    for (int o = 4; o; o >>= 1) {
        p0 += __shfl_down_sync(0xffffffffu, p0, o, 8);
        p1 += __shfl_down_sync(0xffffffffu, p1, o, 8);
        p2 += __shfl_down_sync(0xffffffffu, p2, o, 8);
    }
    if ((tid & 7) == 0 && gn < n) {
        out[gn * 3 + 0] = p0 + b2[0];
        out[gn * 3 + 1] = p1 + b2[1];
        out[gn * 3 + 2] = p2 + b2[2];
    }
}

// ---------------- filter table ----------------
__global__ void table_kernel(const float* __restrict__ m0w0, const float* __restrict__ m0b0,
                             const float* __restrict__ m2w0, const float* __restrict__ m2b0,
                             const float* __restrict__ m0w1, const float* __restrict__ m0b1,
                             const float* __restrict__ m2w1, const float* __restrict__ m2b1,
                             float* __restrict__ wtab) {
    int l = blockIdx.x / NBINS;
    int t = blockIdx.x % NBINS;
    const float* m0w = l ? m0w1 : m0w0;
    const float* m0b = l ? m0b1 : m0b0;
    const float* m2w = l ? m2w1 : m2w0;
    const float* m2b = l ? m2b1 : m2b0;
    __shared__ float hs[H];
    int h = threadIdx.x;
    const float step = CUTOFF / (float)(G_RBF - 1);
    const float coeff = -0.5f / (step * step);
    float acc = m0b[h];
#pragma unroll 10
    for (int g = 0; g < G_RBF; g++) {
        float dd = (float)t - step * (float)g;
        acc += expf(coeff * dd * dd) * m0w[g * H + h];
    }
    hs[h] = sspf(acc);
    __syncthreads();
    float o = m2b[h];
#pragma unroll 16
    for (int k = 0; k < H; k++) o += hs[k] * m2w[k * H + h];
    wtab[(l * NBINS + t) * H + h] = o;
}

// ---------------- CSR build ----------------
__global__ void zero_cnt_kernel(int* __restrict__ cnt) {
    int i = blockIdx.x * blockDim.x + threadIdx.x;
    if (i < N_NODES) cnt[i] = 0;
}
__global__ void hist_kernel(const int* __restrict__ ei, int* __restrict__ cnt) {
    int e = blockIdx.x * blockDim.x + threadIdx.x;
    if (e < N_EDGES) atomicAdd(&cnt[ei[N_EDGES + e]], 1);
}
__global__ void scan1_kernel(const int* __restrict__ cnt, int* __restrict__ off,
                             int* __restrict__ bsum) {
    __shared__ int s[256];
    int t = threadIdx.x;
    int i = blockIdx.x * 256 + t;
    int v = (i < N_NODES) ? cnt[i] : 0;
    s[t] = v;
    __syncthreads();
#pragma unroll
    for (int o = 1; o < 256; o <<= 1) {
        int x = (t >= o) ? s[t - o] : 0;
        __syncthreads();
        s[t] += x;
        __syncthreads();
    }
    if (i < N_NODES) off[i] = s[t] - v;
    if (t == 255) bsum[blockIdx.x] = s[255];
}
__global__ void scan2_kernel(int* __restrict__ bsum) {
    __shared__ int s[256];
    int t = threadIdx.x;
    int v = (t < SCAN_BLOCKS) ? bsum[t] : 0;
    s[t] = v;
    __syncthreads();
#pragma unroll
    for (int o = 1; o < 256; o <<= 1) {
        int x = (t >= o) ? s[t - o] : 0;
        __syncthreads();
        s[t] += x;
        __syncthreads();
    }
    if (t < SCAN_BLOCKS) bsum[t] = s[t] - v;
}
__global__ void scan3_kernel(int* __restrict__ off, const int* __restrict__ bsum,
                             int* __restrict__ pos) {
    int i = blockIdx.x * blockDim.x + threadIdx.x;
    if (i < N_NODES) {
        int o = off[i] + bsum[i >> 8];
        off[i] = o;
        pos[i] = o;
    }
    if (i == 0) off[N_NODES] = N_EDGES;
}
__global__ void scatter_kernel(const int* __restrict__ ei, const float* __restrict__ dist,
                               int* __restrict__ pos, int* __restrict__ jt,
                               float* __restrict__ cs) {
    int e = blockIdx.x * blockDim.x + threadIdx.x;
    if (e >= N_EDGES) return;
    int j = ei[e];
    int i = ei[N_EDGES + e];
    float d = dist[e];
    int tb = (int)d;
    if (tb > NBINS - 1) tb = NBINS - 1;
    float C = 0.5f * cosf(d * (PI_F / CUTOFF)) + 0.5f;
    int p = atomicAdd(&pos[i], 1);
    jt[p] = j | (tb << 27);
    cs[p] = C;
}

// ---------------- aggregate ----------------
__global__ void __launch_bounds__(256) agg_kernel(const float* __restrict__ vlin,
                                                  const int* __restrict__ off,
                                                  const int* __restrict__ jt,
                                                  const float* __restrict__ cs,
                                                  const float* __restrict__ wtab,
                                                  float* __restrict__ agg) {
    __shared__ float4 ws[NBINS * 32];
    int tid = threadIdx.x;
    if (tid < NBINS * 32) ws[tid] = ((const float4*)wtab)[tid];
    __syncthreads();

    int node = blockIdx.x * 8 + (tid >> 5);
    if (node >= N_NODES) return;
    int lane = tid & 31;
    int s = off[node], e = off[node + 1];
    float4 acc = make_float4(0.f, 0.f, 0.f, 0.f);
    const float4* vlin4 = (const float4*)vlin;

    for (int base = s; base < e; base += 32) {
        int m = min(32, e - base);
        int mj = (lane < m) ? jt[base + lane] : 0;
        float mc = (lane < m) ? cs[base + lane] : 0.f;
        int t = 0;
        for (; t + 4 <= m; t += 4) {
            int jv0 = __shfl_sync(0xffffffffu, mj, t);
            int jv1 = __shfl_sync(0xffffffffu, mj, t + 1);
            int jv2 = __shfl_sync(0xffffffffu, mj, t + 2);
            int jv3 = __shfl_sync(0xffffffffu, mj, t + 3);
            float c0 = __shfl_sync(0xffffffffu, mc, t);
            float c1 = __shfl_sync(0xffffffffu, mc, t + 1);
            float c2 = __shfl_sync(0xffffffffu, mc, t + 2);
            float c3 = __shfl_sync(0xffffffffu, mc, t + 3);
            float4 x0 = __ldg(vlin4 + (size_t)(jv0 & 0x07FFFFFF) * 32 + lane);
            float4 x1 = __ldg(vlin4 + (size_t)(jv1 & 0x07FFFFFF) * 32 + lane);
            float4 x2 = __ldg(vlin4 + (size_t)(jv2 & 0x07FFFFFF) * 32 + lane);
            float4 x3 = __ldg(vlin4 + (size_t)(jv3 & 0x07FFFFFF) * 32 + lane);
            float4 w0 = ws[(jv0 >> 27) * 32 + lane];
            float4 w1 = ws[(jv1 >> 27) * 32 + lane];
            float4 w2 = ws[(jv2 >> 27) * 32 + lane];
            float4 w3 = ws[(jv3 >> 27) * 32 + lane];
            acc.x += x0.x * w0.x * c0; acc.y += x0.y * w0.y * c0;
            acc.z += x0.z * w0.z * c0; acc.w += x0.w * w0.w * c0;
            acc.x += x1.x * w1.x * c1; acc.y += x1.y * w1.y * c1;
            acc.z += x1.z * w1.z * c1; acc.w += x1.w * w1.w * c1;
            acc.x += x2.x * w2.x * c2; acc.y += x2.y * w2.y * c2;
            acc.z += x2.z * w2.z * c2; acc.w += x2.w * w2.w * c2;
            acc.x += x3.x * w3.x * c3; acc.y += x3.y * w3.y * c3;
            acc.z += x3.z * w3.z * c3; acc.w += x3.w * w3.w * c3;
        }
        for (; t < m; t++) {
            int jv = __shfl_sync(0xffffffffu, mj, t);
            float c = __shfl_sync(0xffffffffu, mc, t);
            float4 x = __ldg(vlin4 + (size_t)(jv & 0x07FFFFFF) * 32 + lane);
            float4 w = ws[(jv >> 27) * 32 + lane];
            acc.x += x.x * w.x * c;
            acc.y += x.y * w.y * c;
            acc.z += x.z * w.z * c;
            acc.w += x.w * w.w * c;
        }
    }
    ((float4*)agg)[(size_t)node * 32 + lane] = acc;
}

// ---------------- launch ----------------
extern "C" void kernel_launch(void* const* d_in, const int* in_sizes, int n_in,
                              void* d_out, int out_size) {
    const float* z        = (const float*)d_in[0];
    const float* dist     = (const float*)d_in[1];
    const int*   ei       = (const int*)d_in[2];
    const float* init_w   = (const float*)d_in[3];
    const float* init_b   = (const float*)d_in[4];
    const float* e_lin_w[2] = {(const float*)d_in[5],  (const float*)d_in[14]};
    const float* e_m0_w[2]  = {(const float*)d_in[6],  (const float*)d_in[15]};
    const float* e_m0_b[2]  = {(const float*)d_in[7],  (const float*)d_in[16]};
    const float* e_m2_w[2]  = {(const float*)d_in[8],  (const float*)d_in[17]};
    const float* e_m2_b[2]  = {(const float*)d_in[9],  (const float*)d_in[18]};
    const float* v_l1_w[2]  = {(const float*)d_in[10], (const float*)d_in[19]};
    const float* v_l1_b[2]  = {(const float*)d_in[11], (const float*)d_in[20]};
    const float* v_l2_w[2]  = {(const float*)d_in[12], (const float*)d_in[21]};
    const float* v_l2_b[2]  = {(const float*)d_in[13], (const float*)d_in[22]};
    const float* u_l1_w   = (const float*)d_in[23];
    const float* u_l1_b   = (const float*)d_in[24];
    const float* u_l2_w   = (const float*)d_in[25];
    const float* u_l2_b   = (const float*)d_in[26];
    float* out = (float*)d_out;

    float *v, *vlin, *agg, *wtab, *cs;
    uint32_t* wpk;
    int *cnt, *off, *pos, *bsum, *jt;
    cudaGetSymbolAddress((void**)&v,    g_v);
    cudaGetSymbolAddress((void**)&vlin, g_vlin);
    cudaGetSymbolAddress((void**)&agg,  g_agg);
    cudaGetSymbolAddress((void**)&wtab, g_wtab);
    cudaGetSymbolAddress((void**)&wpk,  g_wpk);
    cudaGetSymbolAddress((void**)&cnt,  g_cnt);
    cudaGetSymbolAddress((void**)&off,  g_off);
    cudaGetSymbolAddress((void**)&pos,  g_pos);
    cudaGetSymbolAddress((void**)&bsum, g_bsum);
    cudaGetSymbolAddress((void**)&jt,   g_jt);
    cudaGetSymbolAddress((void**)&cs,   g_cs);

    cudaFuncSetAttribute((const void*)gemm0_fused,
                         cudaFuncAttributeMaxDynamicSharedMemorySize, TCG_SMEM);
    cudaFuncSetAttribute((const void*)mlp_fused<true>,
                         cudaFuncAttributeMaxDynamicSharedMemorySize, TCG_SMEM);
    cudaFuncSetAttribute((const void*)mlp_fused<false>,
                         cudaFuncAttributeMaxDynamicSharedMemorySize, TCG_SMEM);
    cudaFuncSetAttribute((const void*)readout_fused,
                         cudaFuncAttributeMaxDynamicSharedMemorySize, TCG_SMEM);

    const int egrid = (N_EDGES + 255) / 256;
    const int ngrid = (N_NODES + 255) / 256;
    const uint32_t* wm[7];  // 0:e_lin0 1:l1_0 2:l2_0 3:e_lin1 4:l1_1 5:l2_1 6:u1
    for (int i = 0; i < 7; i++) wm[i] = wpk + (size_t)i * WIMG_U32;

    table_kernel<<<2 * NBINS, H>>>(e_m0_w[0], e_m0_b[0], e_m2_w[0], e_m2_b[0],      // 0
                                   e_m0_w[1], e_m0_b[1], e_m2_w[1], e_m2_b[1], wtab);
    {
        dim3 wg(32, 7);
        wsplit_kernel<<<wg, 256>>>(e_lin_w[0], v_l1_w[0], v_l2_w[0],                 // 1
                                   e_lin_w[1], v_l1_w[1], v_l2_w[1], u_l1_w, wpk);
    }
    zero_cnt_kernel<<<ngrid, 256>>>(cnt);                                            // 2
    gemm0_fused<<<N_TILES, 512, TCG_SMEM>>>(z, init_w, init_b, wm[0],                // 3 <- profiled
                                            v, vlin, N_NODES);
    hist_kernel<<<egrid, 256>>>(ei, cnt);                                            // 4
    scan1_kernel<<<SCAN_BLOCKS, 256>>>(cnt, off, bsum);                              // 5
    scan2_kernel<<<1, 256>>>(bsum);                                                  // 6
    scan3_kernel<<<SCAN_BLOCKS, 256>>>(off, bsum, pos);                              // 7
    scatter_kernel<<<egrid, 256>>>(ei, dist, pos, jt, cs);                           // 8

    // layer 0: fused l1 -> ssp -> l2 (+v) -> vlin = v @ e_lin1
    agg_kernel<<<(N_NODES + 7) / 8, 256>>>(vlin, off, jt, cs, wtab, agg);            // 9
    mlp_fused<true><<<N_TILES, 512, TCG_SMEM>>>(agg, wm[1], v_l1_b[0],               // 10
                                                wm[2], v_l2_b[0], v, wm[3], vlin, N_NODES);
    // layer 1
    agg_kernel<<<(N_NODES + 7) / 8, 256>>>(vlin, off, jt, cs, wtab + NBINS * H, agg);// 11
    mlp_fused<false><<<N_TILES, 512, TCG_SMEM>>>(agg, wm[4], v_l1_b[1],              // 12
                                                 wm[5], v_l2_b[1], v, nullptr, nullptr, N_NODES);
    // readout
    readout_fused<<<N_TILES, 512, TCG_SMEM>>>(v, wm[6], u_l1_b, u_l2_w, u_l2_b,      // 13
                                              out, N_NODES);
}

// round 11
// speedup vs baseline: 1.6233x; 1.0182x over previous
#include <cuda_runtime.h>
#include <cuda_bf16.h>
#include <mma.h>
#include <math.h>
#include <stdint.h>

using namespace nvcuda;

#define N_NODES 50000
#define N_EDGES 800000
#define H 128
#define G_RBF 50
#define NBINS 7
#define CUTOFF 6.0f
#define SSP_SHIFT 0.6931471805599453f
#define PI_F 3.14159265358979323846f

#define SCAN_BLOCKS ((N_NODES + 255) / 256)   // 196
#define TILE_M 64
#define N_TILES ((N_NODES + TILE_M - 1) / TILE_M)   // 782
#define WL 136            // bf16 leading dim (128 + 8 pad)
#define OL 132            // f32 output leading dim (128 + 4 pad)
#define WIMG_U32 17408    // per-matrix packed image: hi(8704 u32) + lo(8704 u32)

// smem layout (bytes)
#define SM_AHI 0
#define SM_ALO (TILE_M * WL * 2)                 // 17408
#define SM_BHI (2 * TILE_M * WL * 2)             // 34816
#define SM_BLO (SM_BHI + H * WL * 2)
#define TCG_SMEM (SM_BHI + 2 * H * WL * 2)       // 104448

// ---------------- scratch ----------------
__device__ float g_v[N_NODES * H];
__device__ float g_vlin[N_NODES * H];
__device__ float g_agg[N_NODES * H];
__device__ float g_wtab[2 * NBINS * H];
__device__ uint32_t g_wpk[7 * WIMG_U32];
__device__ int   g_cnt[N_NODES];
__device__ int   g_off[N_NODES + 1];
__device__ int   g_pos[N_NODES];
__device__ int   g_bsum[SCAN_BLOCKS];
__device__ int   g_jt[N_EDGES];
__device__ float g_cs[N_EDGES];

__device__ __forceinline__ float sspf(float x) {
    return fmaxf(x, 0.0f) + log1pf(expf(-fabsf(x))) - SSP_SHIFT;
}

__device__ __forceinline__ uint32_t pack_bf16x2(float x0, float x1) {
    __nv_bfloat16 h0 = __float2bfloat16_rn(x0);
    __nv_bfloat16 h1 = __float2bfloat16_rn(x1);
    return (uint32_t)__bfloat16_as_ushort(h0) |
           ((uint32_t)__bfloat16_as_ushort(h1) << 16);
}

// ---------------- W pre-split ----------------
__global__ void wsplit_kernel(const float* __restrict__ w0, const float* __restrict__ w1,
                              const float* __restrict__ w2, const float* __restrict__ w3,
                              const float* __restrict__ w4, const float* __restrict__ w5,
                              const float* __restrict__ w6, uint32_t* __restrict__ wpk) {
    const float* ws[7] = {w0, w1, w2, w3, w4, w5, w6};
    int m = blockIdx.y;
    const float* W = ws[m];
    int t = blockIdx.x * 256 + threadIdx.x;
    if (t >= 8192) return;
    int n = t & 127;
    int kp = t >> 7;
    float x0 = W[(2 * kp) * H + n];
    float x1 = W[(2 * kp + 1) * H + n];
    float h0 = __bfloat162float(__float2bfloat16_rn(x0));
    float h1 = __bfloat162float(__float2bfloat16_rn(x1));
    uint32_t* base = wpk + (size_t)m * WIMG_U32;
    base[(n * WL + 2 * kp) >> 1]          = pack_bf16x2(x0, x1);
    base[8704 + ((n * WL + 2 * kp) >> 1)] = pack_bf16x2(x0 - h0, x1 - h1);
}

// ================= shared building blocks for tensor kernels =================
// stage B image (70KB contiguous) into smem
__device__ __forceinline__ void stage_B(char* sm, const uint32_t* wpk, int tid) {
    const float4* src = (const float4*)wpk;
    float4* dst = (float4*)(sm + SM_BHI);
    for (int i = tid; i < (2 * H * WL * 2) / 16; i += 512) dst[i] = src[i];
}

// split one float4 (4 consecutive k of one node) into hi/lo bf16 and store
__device__ __forceinline__ void store_A4(char* sm, int node, int c, float4 a) {
    float hx = __bfloat162float(__float2bfloat16_rn(a.x));
    float hy = __bfloat162float(__float2bfloat16_rn(a.y));
    float hz = __bfloat162float(__float2bfloat16_rn(a.z));
    float hw = __bfloat162float(__float2bfloat16_rn(a.w));
    uint32_t boff = 2 * (node * WL + 4 * c);
    *(uint2*)(sm + SM_AHI + boff) = make_uint2(pack_bf16x2(a.x, a.y), pack_bf16x2(a.z, a.w));
    *(uint2*)(sm + SM_ALO + boff) = make_uint2(pack_bf16x2(a.x - hx, a.y - hy),
                                               pack_bf16x2(a.z - hz, a.w - hw));
}

// 3-term bf16-split MMA set over the staged tiles; acc[2] per warp (16x32 tile)
__device__ __forceinline__ void mma_set(const char* sm, int wid,
        wmma::fragment<wmma::accumulator, 16, 16, 16, float>* acc) {
    int wrow = wid & 3, wcol = wid >> 2;
    const __nv_bfloat16* Ahi = (const __nv_bfloat16*)(sm + SM_AHI) + wrow * 16 * WL;
    const __nv_bfloat16* Alo = (const __nv_bfloat16*)(sm + SM_ALO) + wrow * 16 * WL;
    const __nv_bfloat16* Bhi = (const __nv_bfloat16*)(sm + SM_BHI);
    const __nv_bfloat16* Blo = (const __nv_bfloat16*)(sm + SM_BLO);
#pragma unroll
    for (int t = 0; t < 2; t++) wmma::fill_fragment(acc[t], 0.0f);
#pragma unroll
    for (int ks = 0; ks < 8; ks++) {
        wmma::fragment<wmma::matrix_a, 16, 16, 16, __nv_bfloat16, wmma::row_major> ah, al;
        wmma::load_matrix_sync(ah, Ahi + ks * 16, WL);
        wmma::load_matrix_sync(al, Alo + ks * 16, WL);
#pragma unroll
        for (int t = 0; t < 2; t++) {
            int ncol = wcol * 32 + t * 16;
            wmma::fragment<wmma::matrix_b, 16, 16, 16, __nv_bfloat16, wmma::col_major> bh, bl;
            wmma::load_matrix_sync(bh, Bhi + ncol * WL + ks * 16, WL);
            wmma::load_matrix_sync(bl, Blo + ncol * WL + ks * 16, WL);
            wmma::mma_sync(acc[t], ah, bh, acc[t]);
            wmma::mma_sync(acc[t], ah, bl, acc[t]);
            wmma::mma_sync(acc[t], al, bh, acc[t]);
        }
    }
}

// store acc set to osm (overlay on A region). Caller syncs before+after.
__device__ __forceinline__ void store_set(char* sm, int wid,
        wmma::fragment<wmma::accumulator, 16, 16, 16, float>* acc) {
    int wrow = wid & 3, wcol = wid >> 2;
    float* osm = (float*)(sm + SM_AHI);
#pragma unroll
    for (int t = 0; t < 2; t++)
        wmma::store_matrix_sync(osm + wrow * 16 * OL + wcol * 32 + t * 16,
                                acc[t], OL, wmma::mem_row_major);
}

// ---------------- gemm0_fused: v = z@iw+ib (written), vlin = v @ e_lin0 ----------------
__global__ void __launch_bounds__(512, 2) gemm0_fused(const float* __restrict__ z,
                                                      const float* __restrict__ iw,
                                                      const float* __restrict__ ib,
                                                      const uint32_t* __restrict__ wpk,
                                                      float* __restrict__ vout,
                                                      float* __restrict__ vlin, int n) {
    extern __shared__ char sm[];
    int tid = threadIdx.x;
    int nb = blockIdx.x * TILE_M;

    stage_B(sm, wpk, tid);
    for (int idx = tid; idx < TILE_M * 32; idx += 512) {
        int node = idx >> 5, c = idx & 31;
        int gn = nb + node;
        float4 val = make_float4(0.f, 0.f, 0.f, 0.f);
        if (gn < n) {
            float z0 = __ldg(z + gn * 3), z1 = __ldg(z + gn * 3 + 1), z2 = __ldg(z + gn * 3 + 2);
            float4 b  = __ldg((const float4*)ib + c);
            float4 w0 = __ldg((const float4*)iw + c);
            float4 w1 = __ldg((const float4*)iw + 32 + c);
            float4 w2 = __ldg((const float4*)iw + 64 + c);
            val.x = b.x + z0 * w0.x + z1 * w1.x + z2 * w2.x;
            val.y = b.y + z0 * w0.y + z1 * w1.y + z2 * w2.y;
            val.z = b.z + z0 * w0.z + z1 * w1.z + z2 * w2.z;
            val.w = b.w + z0 * w0.w + z1 * w1.w + z2 * w2.w;
            ((float4*)vout)[(size_t)gn * 32 + c] = val;
        }
        store_A4(sm, node, c, val);
    }
    __syncthreads();

    int wid = tid >> 5;
    wmma::fragment<wmma::accumulator, 16, 16, 16, float> acc[2];
    mma_set(sm, wid, acc);
    __syncthreads();
    store_set(sm, wid, acc);
    __syncthreads();

    int node = tid >> 3, cb = (tid & 7) * 16;
    int gn = nb + node;
    if (gn < n) {
        const float* ip = (const float*)(sm + SM_AHI) + node * OL + cb;
        float4* op = (float4*)(vlin + (size_t)gn * H + cb);
#pragma unroll
        for (int i = 0; i < 4; i++)
            op[i] = make_float4(ip[4 * i], ip[4 * i + 1], ip[4 * i + 2], ip[4 * i + 3]);
    }
}

// ---------------- mlp_fused: v += ssp(agg@W1+b1)@W2 + b2 ; opt vlin = v@linW ----------------
template <bool MAKE_VLIN>
__global__ void __launch_bounds__(512, 2) mlp_fused(const float* __restrict__ A,
                                                    const uint32_t* __restrict__ wpk1,
                                                    const float* __restrict__ b1,
                                                    const uint32_t* __restrict__ wpk2,
                                                    const float* __restrict__ b2,
                                                    float* __restrict__ v,
                                                    const uint32_t* __restrict__ wpkL,
                                                    float* __restrict__ vlin, int n) {
    extern __shared__ char sm[];
    __shared__ float bs1[H], bs2[H];
    int tid = threadIdx.x;
    int nb = blockIdx.x * TILE_M;
    if (tid < H) { bs1[tid] = b1[tid]; bs2[tid] = b2[tid]; }

    stage_B(sm, wpk1, tid);
    for (int idx = tid; idx < TILE_M * 32; idx += 512) {
        int node = idx >> 5, c = idx & 31;
        int gn = nb + node;
        float4 val = (gn < n) ? ((const float4*)A)[(size_t)gn * 32 + c]
                              : make_float4(0.f, 0.f, 0.f, 0.f);
        store_A4(sm, node, c, val);
    }
    __syncthreads();

    int wid = tid >> 5;
    int node = tid >> 3, cb = (tid & 7) * 16;
    int gn = nb + node;
    wmma::fragment<wmma::accumulator, 16, 16, 16, float> acc[2];

    // ---- set 1: h = ssp(agg@W1 + b1) ----
    mma_set(sm, wid, acc);
    __syncthreads();
    store_set(sm, wid, acc);
    __syncthreads();

    float t1[16];
    {
        const float* ip = (const float*)(sm + SM_AHI) + node * OL + cb;
#pragma unroll
        for (int i = 0; i < 16; i++) t1[i] = sspf(ip[i] + bs1[cb + i]);
    }
    __syncthreads();   // all osm reads done before A-region rewrite
#pragma unroll
    for (int i = 0; i < 4; i++)
        store_A4(sm, node, (cb >> 2) + i,
                 make_float4(t1[4 * i], t1[4 * i + 1], t1[4 * i + 2], t1[4 * i + 3]));
    stage_B(sm, wpk2, tid);
    __syncthreads();

    // ---- set 2: o = h@W2 + b2 + v ----
    mma_set(sm, wid, acc);
    __syncthreads();
    store_set(sm, wid, acc);
    __syncthreads();

    float o[16];
    {
        const float* ip = (const float*)(sm + SM_AHI) + node * OL + cb;
        if (gn < n) {
            const float* rp = v + (size_t)gn * H + cb;
#pragma unroll
            for (int i = 0; i < 16; i++) o[i] = ip[i] + bs2[cb + i] + rp[i];
            float4* op = (float4*)(v + (size_t)gn * H + cb);
#pragma unroll
            for (int i = 0; i < 4; i++)
                op[i] = make_float4(o[4 * i], o[4 * i + 1], o[4 * i + 2], o[4 * i + 3]);
        } else {
#pragma unroll
            for (int i = 0; i < 16; i++) o[i] = 0.f;
        }
    }

    if (MAKE_VLIN) {
        __syncthreads();   // osm reads done
#pragma unroll
        for (int i = 0; i < 4; i++)
            store_A4(sm, node, (cb >> 2) + i,
                     make_float4(o[4 * i], o[4 * i + 1], o[4 * i + 2], o[4 * i + 3]));
        stage_B(sm, wpkL, tid);
        __syncthreads();

        // ---- set 3: vlin = v_new @ linW ----
        mma_set(sm, wid, acc);
        __syncthreads();
        store_set(sm, wid, acc);
        __syncthreads();

        if (gn < n) {
            const float* ip = (const float*)(sm + SM_AHI) + node * OL + cb;
            float4* op = (float4*)(vlin + (size_t)gn * H + cb);
#pragma unroll
            for (int i = 0; i < 4; i++)
                op[i] = make_float4(ip[4 * i], ip[4 * i + 1], ip[4 * i + 2], ip[4 * i + 3]);
        }
    }
}

// ---------------- readout_fused: out = ssp(v@u1+b1) @ u2 + b2  ([N,3]) ----------------
__global__ void __launch_bounds__(512, 2) readout_fused(const float* __restrict__ A,
                                                        const uint32_t* __restrict__ wpk1,
                                                        const float* __restrict__ b1,
                                                        const float* __restrict__ W2,
                                                        const float* __restrict__ b2,
                                                        float* __restrict__ out, int n) {
    extern __shared__ char sm[];
    __shared__ float bs1[H], ws2[H * 3];
    int tid = threadIdx.x;
    int nb = blockIdx.x * TILE_M;
    if (tid < H) bs1[tid] = b1[tid];
    for (int idx = tid; idx < H * 3; idx += 512) ws2[idx] = W2[idx];

    stage_B(sm, wpk1, tid);
    for (int idx = tid; idx < TILE_M * 32; idx += 512) {
        int node = idx >> 5, c = idx & 31;
        int gn = nb + node;
        float4 val = (gn < n) ? ((const float4*)A)[(size_t)gn * 32 + c]
                              : make_float4(0.f, 0.f, 0.f, 0.f);
        store_A4(sm, node, c, val);
    }
    __syncthreads();

    int wid = tid >> 5;
    wmma::fragment<wmma::accumulator, 16, 16, 16, float> acc[2];
    mma_set(sm, wid, acc);
    __syncthreads();
    store_set(sm, wid, acc);
    __syncthreads();

    int node = tid >> 3, cb = (tid & 7) * 16;
    int gn = nb + node;
    float p0 = 0.f, p1 = 0.f, p2 = 0.f;
    {
        const float* ip = (const float*)(sm + SM_AHI) + node * OL + cb;
#pragma unroll
        for (int i = 0; i < 16; i++) {
            float x = sspf(ip[i] + bs1[cb + i]);
            int col = cb + i;
            p0 += x * ws2[col * 3 + 0];
            p1 += x * ws2[col * 3 + 1];
            p2 += x * ws2[col * 3 + 2];
        }
    }
#pragma unroll
    for (int o = 4; o; o >>= 1) {
        p0 += __shfl_down_sync(0xffffffffu, p0, o, 8);
        p1 += __shfl_down_sync(0xffffffffu, p1, o, 8);
        p2 += __shfl_down_sync(0xffffffffu, p2, o, 8);
    }
    if ((tid & 7) == 0 && gn < n) {
        out[gn * 3 + 0] = p0 + b2[0];
        out[gn * 3 + 1] = p1 + b2[1];
        out[gn * 3 + 2] = p2 + b2[2];
    }
}

// ---------------- filter table ----------------
__global__ void table_kernel(const float* __restrict__ m0w0, const float* __restrict__ m0b0,
                             const float* __restrict__ m2w0, const float* __restrict__ m2b0,
                             const float* __restrict__ m0w1, const float* __restrict__ m0b1,
                             const float* __restrict__ m2w1, const float* __restrict__ m2b1,
                             float* __restrict__ wtab) {
    int l = blockIdx.x / NBINS;
    int t = blockIdx.x % NBINS;
    const float* m0w = l ? m0w1 : m0w0;
    const float* m0b = l ? m0b1 : m0b0;
    const float* m2w = l ? m2w1 : m2w0;
    const float* m2b = l ? m2b1 : m2b0;
    __shared__ float hs[H];
    int h = threadIdx.x;
    const float step = CUTOFF / (float)(G_RBF - 1);
    const float coeff = -0.5f / (step * step);
    float acc = m0b[h];
#pragma unroll 10
    for (int g = 0; g < G_RBF; g++) {
        float dd = (float)t - step * (float)g;
        acc += expf(coeff * dd * dd) * m0w[g * H + h];
    }
    hs[h] = sspf(acc);
    __syncthreads();
    float o = m2b[h];
#pragma unroll 16
    for (int k = 0; k < H; k++) o += hs[k] * m2w[k * H + h];
    wtab[(l * NBINS + t) * H + h] = o;
}

// ---------------- CSR build ----------------
__global__ void zero_cnt_kernel(int* __restrict__ cnt) {
    int i = blockIdx.x * blockDim.x + threadIdx.x;
    if (i < N_NODES) cnt[i] = 0;
}
__global__ void hist_kernel(const int* __restrict__ ei, int* __restrict__ cnt) {
    int e = blockIdx.x * blockDim.x + threadIdx.x;
    if (e < N_EDGES) atomicAdd(&cnt[ei[N_EDGES + e]], 1);
}
__global__ void scan1_kernel(const int* __restrict__ cnt, int* __restrict__ off,
                             int* __restrict__ bsum) {
    __shared__ int s[256];
    int t = threadIdx.x;
    int i = blockIdx.x * 256 + t;
    int v = (i < N_NODES) ? cnt[i] : 0;
    s[t] = v;
    __syncthreads();
#pragma unroll
    for (int o = 1; o < 256; o <<= 1) {
        int x = (t >= o) ? s[t - o] : 0;
        __syncthreads();
        s[t] += x;
        __syncthreads();
    }
    if (i < N_NODES) off[i] = s[t] - v;
    if (t == 255) bsum[blockIdx.x] = s[255];
}
__global__ void scan2_kernel(int* __restrict__ bsum) {
    __shared__ int s[256];
    int t = threadIdx.x;
    int v = (t < SCAN_BLOCKS) ? bsum[t] : 0;
    s[t] = v;
    __syncthreads();
#pragma unroll
    for (int o = 1; o < 256; o <<= 1) {
        int x = (t >= o) ? s[t - o] : 0;
        __syncthreads();
        s[t] += x;
        __syncthreads();
    }
    if (t < SCAN_BLOCKS) bsum[t] = s[t] - v;
}
__global__ void scan3_kernel(int* __restrict__ off, const int* __restrict__ bsum,
                             int* __restrict__ pos) {
    int i = blockIdx.x * blockDim.x + threadIdx.x;
    if (i < N_NODES) {
        int o = off[i] + bsum[i >> 8];
        off[i] = o;
        pos[i] = o;
    }
    if (i == 0) off[N_NODES] = N_EDGES;
}
__global__ void scatter_kernel(const int* __restrict__ ei, const float* __restrict__ dist,
                               int* __restrict__ pos, int* __restrict__ jt,
                               float* __restrict__ cs) {
    int e = blockIdx.x * blockDim.x + threadIdx.x;
    if (e >= N_EDGES) return;
    int j = ei[e];
    int i = ei[N_EDGES + e];
    float d = dist[e];
    int tb = (int)d;
    if (tb > NBINS - 1) tb = NBINS - 1;
    float C = 0.5f * cosf(d * (PI_F / CUTOFF)) + 0.5f;
    int p = atomicAdd(&pos[i], 1);
    jt[p] = j | (tb << 27);
    cs[p] = C;
}

// ---------------- aggregate ----------------
__global__ void __launch_bounds__(256) agg_kernel(const float* __restrict__ vlin,
                                                  const int* __restrict__ off,
                                                  const int* __restrict__ jt,
                                                  const float* __restrict__ cs,
                                                  const float* __restrict__ wtab,
                                                  float* __restrict__ agg) {
    __shared__ float4 ws[NBINS * 32];
    int tid = threadIdx.x;
    if (tid < NBINS * 32) ws[tid] = ((const float4*)wtab)[tid];
    __syncthreads();

    int node = blockIdx.x * 8 + (tid >> 5);
    if (node >= N_NODES) return;
    int lane = tid & 31;
    int s = off[node], e = off[node + 1];
    float4 acc = make_float4(0.f, 0.f, 0.f, 0.f);
    const float4* vlin4 = (const float4*)vlin;

    for (int base = s; base < e; base += 32) {
        int m = min(32, e - base);
        int mj = (lane < m) ? jt[base + lane] : 0;
        float mc = (lane < m) ? cs[base + lane] : 0.f;
        int t = 0;
        for (; t + 4 <= m; t += 4) {
            int jv0 = __shfl_sync(0xffffffffu, mj, t);
            int jv1 = __shfl_sync(0xffffffffu, mj, t + 1);
            int jv2 = __shfl_sync(0xffffffffu, mj, t + 2);
            int jv3 = __shfl_sync(0xffffffffu, mj, t + 3);
            float c0 = __shfl_sync(0xffffffffu, mc, t);
            float c1 = __shfl_sync(0xffffffffu, mc, t + 1);
            float c2 = __shfl_sync(0xffffffffu, mc, t + 2);
            float c3 = __shfl_sync(0xffffffffu, mc, t + 3);
            float4 x0 = __ldg(vlin4 + (size_t)(jv0 & 0x07FFFFFF) * 32 + lane);
            float4 x1 = __ldg(vlin4 + (size_t)(jv1 & 0x07FFFFFF) * 32 + lane);
            float4 x2 = __ldg(vlin4 + (size_t)(jv2 & 0x07FFFFFF) * 32 + lane);
            float4 x3 = __ldg(vlin4 + (size_t)(jv3 & 0x07FFFFFF) * 32 + lane);
            float4 w0 = ws[(jv0 >> 27) * 32 + lane];
            float4 w1 = ws[(jv1 >> 27) * 32 + lane];
            float4 w2 = ws[(jv2 >> 27) * 32 + lane];
            float4 w3 = ws[(jv3 >> 27) * 32 + lane];
            acc.x += x0.x * w0.x * c0; acc.y += x0.y * w0.y * c0;
            acc.z += x0.z * w0.z * c0; acc.w += x0.w * w0.w * c0;
            acc.x += x1.x * w1.x * c1; acc.y += x1.y * w1.y * c1;
            acc.z += x1.z * w1.z * c1; acc.w += x1.w * w1.w * c1;
            acc.x += x2.x * w2.x * c2; acc.y += x2.y * w2.y * c2;
            acc.z += x2.z * w2.z * c2; acc.w += x2.w * w2.w * c2;
            acc.x += x3.x * w3.x * c3; acc.y += x3.y * w3.y * c3;
            acc.z += x3.z * w3.z * c3; acc.w += x3.w * w3.w * c3;
        }
        for (; t < m; t++) {
            int jv = __shfl_sync(0xffffffffu, mj, t);
            float c = __shfl_sync(0xffffffffu, mc, t);
            float4 x = __ldg(vlin4 + (size_t)(jv & 0x07FFFFFF) * 32 + lane);
            float4 w = ws[(jv >> 27) * 32 + lane];
            acc.x += x.x * w.x * c;
            acc.y += x.y * w.y * c;
            acc.z += x.z * w.z * c;
            acc.w += x.w * w.w * c;
        }
    }
    ((float4*)agg)[(size_t)node * 32 + lane] = acc;
}

// ---------------- launch ----------------
extern "C" void kernel_launch(void* const* d_in, const int* in_sizes, int n_in,
                              void* d_out, int out_size) {
    const float* z        = (const float*)d_in[0];
    const float* dist     = (const float*)d_in[1];
    const int*   ei       = (const int*)d_in[2];
    const float* init_w   = (const float*)d_in[3];
    const float* init_b   = (const float*)d_in[4];
    const float* e_lin_w[2] = {(const float*)d_in[5],  (const float*)d_in[14]};
    const float* e_m0_w[2]  = {(const float*)d_in[6],  (const float*)d_in[15]};
    const float* e_m0_b[2]  = {(const float*)d_in[7],  (const float*)d_in[16]};
    const float* e_m2_w[2]  = {(const float*)d_in[8],  (const float*)d_in[17]};
    const float* e_m2_b[2]  = {(const float*)d_in[9],  (const float*)d_in[18]};
    const float* v_l1_w[2]  = {(const float*)d_in[10], (const float*)d_in[19]};
    const float* v_l1_b[2]  = {(const float*)d_in[11], (const float*)d_in[20]};
    const float* v_l2_w[2]  = {(const float*)d_in[12], (const float*)d_in[21]};
    const float* v_l2_b[2]  = {(const float*)d_in[13], (const float*)d_in[22]};
    const float* u_l1_w   = (const float*)d_in[23];
    const float* u_l1_b   = (const float*)d_in[24];
    const float* u_l2_w   = (const float*)d_in[25];
    const float* u_l2_b   = (const float*)d_in[26];
    float* out = (float*)d_out;

    float *v, *vlin, *agg, *wtab, *cs;
    uint32_t* wpk;
    int *cnt, *off, *pos, *bsum, *jt;
    cudaGetSymbolAddress((void**)&v,    g_v);
    cudaGetSymbolAddress((void**)&vlin, g_vlin);
    cudaGetSymbolAddress((void**)&agg,  g_agg);
    cudaGetSymbolAddress((void**)&wtab, g_wtab);
    cudaGetSymbolAddress((void**)&wpk,  g_wpk);
    cudaGetSymbolAddress((void**)&cnt,  g_cnt);
    cudaGetSymbolAddress((void**)&off,  g_off);
    cudaGetSymbolAddress((void**)&pos,  g_pos);
    cudaGetSymbolAddress((void**)&bsum, g_bsum);
    cudaGetSymbolAddress((void**)&jt,   g_jt);
    cudaGetSymbolAddress((void**)&cs,   g_cs);

    cudaFuncSetAttribute((const void*)gemm0_fused,
                         cudaFuncAttributeMaxDynamicSharedMemorySize, TCG_SMEM);
    cudaFuncSetAttribute((const void*)mlp_fused<true>,
                         cudaFuncAttributeMaxDynamicSharedMemorySize, TCG_SMEM);
    cudaFuncSetAttribute((const void*)mlp_fused<false>,
                         cudaFuncAttributeMaxDynamicSharedMemorySize, TCG_SMEM);
    cudaFuncSetAttribute((const void*)readout_fused,
                         cudaFuncAttributeMaxDynamicSharedMemorySize, TCG_SMEM);

    const int egrid = (N_EDGES + 255) / 256;
    const int ngrid = (N_NODES + 255) / 256;
    const uint32_t* wm[7];  // 0:e_lin0 1:l1_0 2:l2_0 3:e_lin1 4:l1_1 5:l2_1 6:u1
    for (int i = 0; i < 7; i++) wm[i] = wpk + (size_t)i * WIMG_U32;

    table_kernel<<<2 * NBINS, H>>>(e_m0_w[0], e_m0_b[0], e_m2_w[0], e_m2_b[0],      // 0
                                   e_m0_w[1], e_m0_b[1], e_m2_w[1], e_m2_b[1], wtab);
    {
        dim3 wg(32, 7);
        wsplit_kernel<<<wg, 256>>>(e_lin_w[0], v_l1_w[0], v_l2_w[0],                 // 1
                                   e_lin_w[1], v_l1_w[1], v_l2_w[1], u_l1_w, wpk);
    }
    zero_cnt_kernel<<<ngrid, 256>>>(cnt);                                            // 2
    gemm0_fused<<<N_TILES, 512, TCG_SMEM>>>(z, init_w, init_b, wm[0],                // 3 <- profiled
                                            v, vlin, N_NODES);
    hist_kernel<<<egrid, 256>>>(ei, cnt);                                            // 4
    scan1_kernel<<<SCAN_BLOCKS, 256>>>(cnt, off, bsum);                              // 5
    scan2_kernel<<<1, 256>>>(bsum);                                                  // 6
    scan3_kernel<<<SCAN_BLOCKS, 256>>>(off, bsum, pos);                              // 7
    scatter_kernel<<<egrid, 256>>>(ei, dist, pos, jt, cs);                           // 8

    // layer 0: fused l1 -> ssp -> l2 (+v) -> vlin = v @ e_lin1
    agg_kernel<<<(N_NODES + 7) / 8, 256>>>(vlin, off, jt, cs, wtab, agg);            // 9
    mlp_fused<true><<<N_TILES, 512, TCG_SMEM>>>(agg, wm[1], v_l1_b[0],               // 10
                                                wm[2], v_l2_b[0], v, wm[3], vlin, N_NODES);
    // layer 1
    agg_kernel<<<(N_NODES + 7) / 8, 256>>>(vlin, off, jt, cs, wtab + NBINS * H, agg);// 11
    mlp_fused<false><<<N_TILES, 512, TCG_SMEM>>>(agg, wm[4], v_l1_b[1],              // 12
                                                 wm[5], v_l2_b[1], v, nullptr, nullptr, N_NODES);
    // readout
    readout_fused<<<N_TILES, 512, TCG_SMEM>>>(v, wm[6], u_l1_b, u_l2_w, u_l2_b,      // 13
                                              out, N_NODES);
}

// round 13
// speedup vs baseline: 1.6243x; 1.0006x over previous
#include <cuda_runtime.h>
#include <cuda_bf16.h>
#include <mma.h>
#include <math.h>
#include <stdint.h>

using namespace nvcuda;

#define N_NODES 50000
#define N_EDGES 800000
#define H 128
#define G_RBF 50
#define NBINS 7
#define CUTOFF 6.0f
#define SSP_SHIFT 0.6931471805599453f
#define PI_F 3.14159265358979323846f

#define SCAN_BLOCKS ((N_NODES + 255) / 256)   // 196
#define TILE_M 64
#define N_TILES ((N_NODES + TILE_M - 1) / TILE_M)   // 782
#define WL 136            // bf16 leading dim (128 + 8 pad)
#define OL 132            // f32 output leading dim (128 + 4 pad)
#define WIMG_U32 17408    // per-matrix packed image: hi(8704 u32) + lo(8704 u32)

// smem layout (bytes)
#define SM_AHI 0
#define SM_ALO (TILE_M * WL * 2)                 // 17408
#define SM_BHI (2 * TILE_M * WL * 2)             // 34816
#define SM_BLO (SM_BHI + H * WL * 2)
#define TCG_SMEM (SM_BHI + 2 * H * WL * 2)       // 104448

// ---------------- scratch ----------------
__device__ float  g_v[N_NODES * H];
__device__ float  g_vlin[N_NODES * H];
__device__ float  g_agg[N_NODES * H];
__device__ float  g_wtab[2 * NBINS * H];
__device__ uint32_t g_wpk[7 * WIMG_U32];
__device__ int   g_cnt[N_NODES];
__device__ int   g_off[N_NODES + 1];
__device__ int   g_pos[N_NODES];
__device__ int   g_bsum[SCAN_BLOCKS];
__device__ int   g_jt[N_EDGES];
__device__ float g_cs[N_EDGES];

__device__ __forceinline__ float sspf(float x) {
    return fmaxf(x, 0.0f) + log1pf(expf(-fabsf(x))) - SSP_SHIFT;
}

__device__ __forceinline__ uint32_t pack_bf16x2(float x0, float x1) {
    __nv_bfloat16 h0 = __float2bfloat16_rn(x0);
    __nv_bfloat16 h1 = __float2bfloat16_rn(x1);
    return (uint32_t)__bfloat16_as_ushort(h0) |
           ((uint32_t)__bfloat16_as_ushort(h1) << 16);
}

// ---------------- W pre-split ----------------
__global__ void wsplit_kernel(const float* __restrict__ w0, const float* __restrict__ w1,
                              const float* __restrict__ w2, const float* __restrict__ w3,
                              const float* __restrict__ w4, const float* __restrict__ w5,
                              const float* __restrict__ w6, uint32_t* __restrict__ wpk) {
    const float* ws[7] = {w0, w1, w2, w3, w4, w5, w6};
    int m = blockIdx.y;
    const float* W = ws[m];
    int t = blockIdx.x * 256 + threadIdx.x;
    if (t >= 8192) return;
    int n = t & 127;
    int kp = t >> 7;
    float x0 = W[(2 * kp) * H + n];
    float x1 = W[(2 * kp + 1) * H + n];
    float h0 = __bfloat162float(__float2bfloat16_rn(x0));
    float h1 = __bfloat162float(__float2bfloat16_rn(x1));
    uint32_t* base = wpk + (size_t)m * WIMG_U32;
    base[(n * WL + 2 * kp) >> 1]          = pack_bf16x2(x0, x1);
    base[8704 + ((n * WL + 2 * kp) >> 1)] = pack_bf16x2(x0 - h0, x1 - h1);
}

// ================= shared building blocks =================
__device__ __forceinline__ void stage_B(char* sm, const uint32_t* wpk, int tid) {
    const float4* src = (const float4*)wpk;
    float4* dst = (float4*)(sm + SM_BHI);
    for (int i = tid; i < (2 * H * WL * 2) / 16; i += 512) dst[i] = src[i];
}

__device__ __forceinline__ void store_A4(char* sm, int node, int c, float4 a) {
    float hx = __bfloat162float(__float2bfloat16_rn(a.x));
    float hy = __bfloat162float(__float2bfloat16_rn(a.y));
    float hz = __bfloat162float(__float2bfloat16_rn(a.z));
    float hw = __bfloat162float(__float2bfloat16_rn(a.w));
    uint32_t boff = 2 * (node * WL + 4 * c);
    *(uint2*)(sm + SM_AHI + boff) = make_uint2(pack_bf16x2(a.x, a.y), pack_bf16x2(a.z, a.w));
    *(uint2*)(sm + SM_ALO + boff) = make_uint2(pack_bf16x2(a.x - hx, a.y - hy),
                                               pack_bf16x2(a.z - hz, a.w - hw));
}

__device__ __forceinline__ void mma_set(const char* sm, int wid,
        wmma::fragment<wmma::accumulator, 16, 16, 16, float>* acc) {
    int wrow = wid & 3, wcol = wid >> 2;
    const __nv_bfloat16* Ahi = (const __nv_bfloat16*)(sm + SM_AHI) + wrow * 16 * WL;
    const __nv_bfloat16* Alo = (const __nv_bfloat16*)(sm + SM_ALO) + wrow * 16 * WL;
    const __nv_bfloat16* Bhi = (const __nv_bfloat16*)(sm + SM_BHI);
    const __nv_bfloat16* Blo = (const __nv_bfloat16*)(sm + SM_BLO);
#pragma unroll
    for (int t = 0; t < 2; t++) wmma::fill_fragment(acc[t], 0.0f);
#pragma unroll
    for (int ks = 0; ks < 8; ks++) {
        wmma::fragment<wmma::matrix_a, 16, 16, 16, __nv_bfloat16, wmma::row_major> ah, al;
        wmma::load_matrix_sync(ah, Ahi + ks * 16, WL);
        wmma::load_matrix_sync(al, Alo + ks * 16, WL);
#pragma unroll
        for (int t = 0; t < 2; t++) {
            int ncol = wcol * 32 + t * 16;
            wmma::fragment<wmma::matrix_b, 16, 16, 16, __nv_bfloat16, wmma::col_major> bh, bl;
            wmma::load_matrix_sync(bh, Bhi + ncol * WL + ks * 16, WL);
            wmma::load_matrix_sync(bl, Blo + ncol * WL + ks * 16, WL);
            wmma::mma_sync(acc[t], ah, bh, acc[t]);
            wmma::mma_sync(acc[t], ah, bl, acc[t]);
            wmma::mma_sync(acc[t], al, bh, acc[t]);
        }
    }
}

__device__ __forceinline__ void store_set(char* sm, int wid,
        wmma::fragment<wmma::accumulator, 16, 16, 16, float>* acc) {
    int wrow = wid & 3, wcol = wid >> 2;
    float* osm = (float*)(sm + SM_AHI);
#pragma unroll
    for (int t = 0; t < 2; t++)
        wmma::store_matrix_sync(osm + wrow * 16 * OL + wcol * 32 + t * 16,
                                acc[t], OL, wmma::mem_row_major);
}

// ---------------- gemm0_fused: v = z@iw+ib (written), vlin = v @ e_lin0 ----------------
__global__ void __launch_bounds__(512, 2) gemm0_fused(const float* __restrict__ z,
                                                      const float* __restrict__ iw,
                                                      const float* __restrict__ ib,
                                                      const uint32_t* __restrict__ wpk,
                                                      float* __restrict__ vout,
                                                      float* __restrict__ vlin, int n) {
    extern __shared__ char sm[];
    int tid = threadIdx.x;
    int nb = blockIdx.x * TILE_M;

    stage_B(sm, wpk, tid);
    for (int idx = tid; idx < TILE_M * 32; idx += 512) {
        int node = idx >> 5, c = idx & 31;
        int gn = nb + node;
        float4 val = make_float4(0.f, 0.f, 0.f, 0.f);
        if (gn < n) {
            float z0 = __ldg(z + gn * 3), z1 = __ldg(z + gn * 3 + 1), z2 = __ldg(z + gn * 3 + 2);
            float4 b  = __ldg((const float4*)ib + c);
            float4 w0 = __ldg((const float4*)iw + c);
            float4 w1 = __ldg((const float4*)iw + 32 + c);
            float4 w2 = __ldg((const float4*)iw + 64 + c);
            val.x = b.x + z0 * w0.x + z1 * w1.x + z2 * w2.x;
            val.y = b.y + z0 * w0.y + z1 * w1.y + z2 * w2.y;
            val.z = b.z + z0 * w0.z + z1 * w1.z + z2 * w2.z;
            val.w = b.w + z0 * w0.w + z1 * w1.w + z2 * w2.w;
            ((float4*)vout)[(size_t)gn * 32 + c] = val;
        }
        store_A4(sm, node, c, val);
    }
    __syncthreads();

    int wid = tid >> 5;
    wmma::fragment<wmma::accumulator, 16, 16, 16, float> acc[2];
    mma_set(sm, wid, acc);
    __syncthreads();
    store_set(sm, wid, acc);
    __syncthreads();

    int node = tid >> 3, cb = (tid & 7) * 16;
    int gn = nb + node;
    if (gn < n) {
        const float* ip = (const float*)(sm + SM_AHI) + node * OL + cb;
        float4* op = (float4*)(vlin + (size_t)gn * H + cb);
#pragma unroll
        for (int i = 0; i < 4; i++)
            op[i] = make_float4(ip[4 * i], ip[4 * i + 1], ip[4 * i + 2], ip[4 * i + 3]);
    }
}

// ---------------- mlp_fused (layer 0): v += ssp(agg@W1+b1)@W2+b2 ; vlin = v@linW ----------------
__global__ void __launch_bounds__(512, 2) mlp_fused(const float* __restrict__ A,
                                                    const uint32_t* __restrict__ wpk1,
                                                    const float* __restrict__ b1,
                                                    const uint32_t* __restrict__ wpk2,
                                                    const float* __restrict__ b2,
                                                    float* __restrict__ v,
                                                    const uint32_t* __restrict__ wpkL,
                                                    float* __restrict__ vlin, int n) {
    extern __shared__ char sm[];
    __shared__ float bs1[H], bs2[H];
    int tid = threadIdx.x;
    int nb = blockIdx.x * TILE_M;
    if (tid < H) { bs1[tid] = b1[tid]; bs2[tid] = b2[tid]; }

    stage_B(sm, wpk1, tid);
    for (int idx = tid; idx < TILE_M * 32; idx += 512) {
        int node = idx >> 5, c = idx & 31;
        int gn = nb + node;
        float4 val = (gn < n) ? ((const float4*)A)[(size_t)gn * 32 + c]
                              : make_float4(0.f, 0.f, 0.f, 0.f);
        store_A4(sm, node, c, val);
    }
    __syncthreads();

    int wid = tid >> 5;
    int node = tid >> 3, cb = (tid & 7) * 16;
    int gn = nb + node;
    wmma::fragment<wmma::accumulator, 16, 16, 16, float> acc[2];

    // set 1: h = ssp(agg@W1 + b1)
    mma_set(sm, wid, acc);
    __syncthreads();
    store_set(sm, wid, acc);
    __syncthreads();

    float t1[16];
    {
        const float* ip = (const float*)(sm + SM_AHI) + node * OL + cb;
#pragma unroll
        for (int i = 0; i < 16; i++) t1[i] = sspf(ip[i] + bs1[cb + i]);
    }
    __syncthreads();
#pragma unroll
    for (int i = 0; i < 4; i++)
        store_A4(sm, node, (cb >> 2) + i,
                 make_float4(t1[4 * i], t1[4 * i + 1], t1[4 * i + 2], t1[4 * i + 3]));
    stage_B(sm, wpk2, tid);
    __syncthreads();

    // set 2: o = h@W2 + b2 + v   (write v)
    mma_set(sm, wid, acc);
    __syncthreads();
    store_set(sm, wid, acc);
    __syncthreads();

    float o[16];
    {
        const float* ip = (const float*)(sm + SM_AHI) + node * OL + cb;
        if (gn < n) {
            const float* rp = v + (size_t)gn * H + cb;
#pragma unroll
            for (int i = 0; i < 16; i++) o[i] = ip[i] + bs2[cb + i] + rp[i];
            float4* op = (float4*)(v + (size_t)gn * H + cb);
#pragma unroll
            for (int i = 0; i < 4; i++)
                op[i] = make_float4(o[4 * i], o[4 * i + 1], o[4 * i + 2], o[4 * i + 3]);
        } else {
#pragma unroll
            for (int i = 0; i < 16; i++) o[i] = 0.f;
        }
    }
    __syncthreads();
#pragma unroll
    for (int i = 0; i < 4; i++)
        store_A4(sm, node, (cb >> 2) + i,
                 make_float4(o[4 * i], o[4 * i + 1], o[4 * i + 2], o[4 * i + 3]));
    stage_B(sm, wpkL, tid);
    __syncthreads();

    // set 3: vlin = v_new @ linW
    mma_set(sm, wid, acc);
    __syncthreads();
    store_set(sm, wid, acc);
    __syncthreads();

    if (gn < n) {
        const float* ip = (const float*)(sm + SM_AHI) + node * OL + cb;
        float4* op = (float4*)(vlin + (size_t)gn * H + cb);
#pragma unroll
        for (int i = 0; i < 4; i++)
            op[i] = make_float4(ip[4 * i], ip[4 * i + 1], ip[4 * i + 2], ip[4 * i + 3]);
    }
}

// ---------------- mlp_readout_fused (layer 1 + readout) ----------------
// h = ssp(agg@W1+b1); vn = h@W2+b2+v; hu = ssp(vn@U1+bu); out = hu@U2 + b2u
__global__ void __launch_bounds__(512, 2) mlp_readout_fused(const float* __restrict__ A,
                                                            const uint32_t* __restrict__ wpk1,
                                                            const float* __restrict__ b1,
                                                            const uint32_t* __restrict__ wpk2,
                                                            const float* __restrict__ b2,
                                                            const float* __restrict__ v,
                                                            const uint32_t* __restrict__ wpkU,
                                                            const float* __restrict__ bu,
                                                            const float* __restrict__ U2,
                                                            const float* __restrict__ b2u,
                                                            float* __restrict__ out, int n) {
    extern __shared__ char sm[];
    __shared__ float bs1[H], bs2[H], bsu[H], ws2[H * 3];
    int tid = threadIdx.x;
    int nb = blockIdx.x * TILE_M;
    if (tid < H) { bs1[tid] = b1[tid]; bs2[tid] = b2[tid]; bsu[tid] = bu[tid]; }
    for (int idx = tid; idx < H * 3; idx += 512) ws2[idx] = U2[idx];

    stage_B(sm, wpk1, tid);
    for (int idx = tid; idx < TILE_M * 32; idx += 512) {
        int node = idx >> 5, c = idx & 31;
        int gn = nb + node;
        float4 val = (gn < n) ? ((const float4*)A)[(size_t)gn * 32 + c]
                              : make_float4(0.f, 0.f, 0.f, 0.f);
        store_A4(sm, node, c, val);
    }
    __syncthreads();

    int wid = tid >> 5;
    int node = tid >> 3, cb = (tid & 7) * 16;
    int gn = nb + node;
    wmma::fragment<wmma::accumulator, 16, 16, 16, float> acc[2];

    // set 1
    mma_set(sm, wid, acc);
    __syncthreads();
    store_set(sm, wid, acc);
    __syncthreads();

    float t1[16];
    {
        const float* ip = (const float*)(sm + SM_AHI) + node * OL + cb;
#pragma unroll
        for (int i = 0; i < 16; i++) t1[i] = sspf(ip[i] + bs1[cb + i]);
    }
    __syncthreads();
#pragma unroll
    for (int i = 0; i < 4; i++)
        store_A4(sm, node, (cb >> 2) + i,
                 make_float4(t1[4 * i], t1[4 * i + 1], t1[4 * i + 2], t1[4 * i + 3]));
    stage_B(sm, wpk2, tid);
    __syncthreads();

    // set 2: vn = h@W2 + b2 + v   (no global write)
    mma_set(sm, wid, acc);
    __syncthreads();
    store_set(sm, wid, acc);
    __syncthreads();

    float o[16];
    {
        const float* ip = (const float*)(sm + SM_AHI) + node * OL + cb;
        if (gn < n) {
            const float* rp = v + (size_t)gn * H + cb;
#pragma unroll
            for (int i = 0; i < 16; i++) o[i] = ip[i] + bs2[cb + i] + rp[i];
        } else {
#pragma unroll
            for (int i = 0; i < 16; i++) o[i] = 0.f;
        }
    }
    __syncthreads();
#pragma unroll
    for (int i = 0; i < 4; i++)
        store_A4(sm, node, (cb >> 2) + i,
                 make_float4(o[4 * i], o[4 * i + 1], o[4 * i + 2], o[4 * i + 3]));
    stage_B(sm, wpkU, tid);
    __syncthreads();

    // set 3: hu = ssp(vn@U1 + bu); project to 3 and reduce
    mma_set(sm, wid, acc);
    __syncthreads();
    store_set(sm, wid, acc);
    __syncthreads();

    float p0 = 0.f, p1 = 0.f, p2 = 0.f;
    {
        const float* ip = (const float*)(sm + SM_AHI) + node * OL + cb;
#pragma unroll
        for (int i = 0; i < 16; i++) {
            float x = sspf(ip[i] + bsu[cb + i]);
            int col = cb + i;
            p0 += x * ws2[col * 3 + 0];
            p1 += x * ws2[col * 3 + 1];
            p2 += x * ws2[col * 3 + 2];
        }
    }
#pragma unroll
    for (int off = 4; off; off >>= 1) {
        p0 += __shfl_down_sync(0xffffffffu, p0, off, 8);
        p1 += __shfl_down_sync(0xffffffffu, p1, off, 8);
        p2 += __shfl_down_sync(0xffffffffu, p2, off, 8);
    }
    if ((tid & 7) == 0 && gn < n) {
        out[gn * 3 + 0] = p0 + b2u[0];
        out[gn * 3 + 1] = p1 + b2u[1];
        out[gn * 3 + 2] = p2 + b2u[2];
    }
}

// ---------------- filter table ----------------
__global__ void table_kernel(const float* __restrict__ m0w0, const float* __restrict__ m0b0,
                             const float* __restrict__ m2w0, const float* __restrict__ m2b0,
                             const float* __restrict__ m0w1, const float* __restrict__ m0b1,
                             const float* __restrict__ m2w1, const float* __restrict__ m2b1,
                             float* __restrict__ wtab) {
    int l = blockIdx.x / NBINS;
    int t = blockIdx.x % NBINS;
    const float* m0w = l ? m0w1 : m0w0;
    const float* m0b = l ? m0b1 : m0b0;
    const float* m2w = l ? m2w1 : m2w0;
    const float* m2b = l ? m2b1 : m2b0;
    __shared__ float hs[H];
    int h = threadIdx.x;
    const float step = CUTOFF / (float)(G_RBF - 1);
    const float coeff = -0.5f / (step * step);
    float acc = m0b[h];
#pragma unroll 10
    for (int g = 0; g < G_RBF; g++) {
        float dd = (float)t - step * (float)g;
        acc += expf(coeff * dd * dd) * m0w[g * H + h];
    }
    hs[h] = sspf(acc);
    __syncthreads();
    float o = m2b[h];
#pragma unroll 16
    for (int k = 0; k < H; k++) o += hs[k] * m2w[k * H + h];
    wtab[(l * NBINS + t) * H + h] = o;
}

// ---------------- CSR build ----------------
__global__ void zero_cnt_kernel(int* __restrict__ cnt) {
    int i = blockIdx.x * blockDim.x + threadIdx.x;
    if (i < N_NODES) cnt[i] = 0;
}
__global__ void hist_kernel(const int* __restrict__ ei, int* __restrict__ cnt) {
    int e = blockIdx.x * blockDim.x + threadIdx.x;
    if (e < N_EDGES) atomicAdd(&cnt[ei[N_EDGES + e]], 1);
}
__global__ void scan1_kernel(const int* __restrict__ cnt, int* __restrict__ off,
                             int* __restrict__ bsum) {
    __shared__ int s[256];
    int t = threadIdx.x;
    int i = blockIdx.x * 256 + t;
    int v = (i < N_NODES) ? cnt[i] : 0;
    s[t] = v;
    __syncthreads();
#pragma unroll
    for (int o = 1; o < 256; o <<= 1) {
        int x = (t >= o) ? s[t - o] : 0;
        __syncthreads();
        s[t] += x;
        __syncthreads();
    }
    if (i < N_NODES) off[i] = s[t] - v;
    if (t == 255) bsum[blockIdx.x] = s[255];
}
__global__ void scan2_kernel(int* __restrict__ bsum) {
    __shared__ int s[256];
    int t = threadIdx.x;
    int v = (t < SCAN_BLOCKS) ? bsum[t] : 0;
    s[t] = v;
    __syncthreads();
#pragma unroll
    for (int o = 1; o < 256; o <<= 1) {
        int x = (t >= o) ? s[t - o] : 0;
        __syncthreads();
        s[t] += x;
        __syncthreads();
    }
    if (t < SCAN_BLOCKS) bsum[t] = s[t] - v;
}
__global__ void scan3_kernel(int* __restrict__ off, const int* __restrict__ bsum,
                             int* __restrict__ pos) {
    int i = blockIdx.x * blockDim.x + threadIdx.x;
    if (i < N_NODES) {
        int o = off[i] + bsum[i >> 8];
        off[i] = o;
        pos[i] = o;
    }
    if (i == 0) off[N_NODES] = N_EDGES;
}
__global__ void scatter_kernel(const int* __restrict__ ei, const float* __restrict__ dist,
                               int* __restrict__ pos, int* __restrict__ jt,
                               float* __restrict__ cs) {
    int e = blockIdx.x * blockDim.x + threadIdx.x;
    if (e >= N_EDGES) return;
    int j = ei[e];
    int i = ei[N_EDGES + e];
    float d = dist[e];
    int tb = (int)d;
    if (tb > NBINS - 1) tb = NBINS - 1;
    float C = 0.5f * cosf(d * (PI_F / CUTOFF)) + 0.5f;
    int p = atomicAdd(&pos[i], 1);
    jt[p] = j | (tb << 27);
    cs[p] = C;
}

// ---------------- aggregate (fp32 vlin) ----------------
__global__ void __launch_bounds__(256) agg_kernel(const float* __restrict__ vlin,
                                                  const int* __restrict__ off,
                                                  const int* __restrict__ jt,
                                                  const float* __restrict__ cs,
                                                  const float* __restrict__ wtab,
                                                  float* __restrict__ agg) {
    __shared__ float4 ws[NBINS * 32];
    int tid = threadIdx.x;
    if (tid < NBINS * 32) ws[tid] = ((const float4*)wtab)[tid];
    __syncthreads();

    int node = blockIdx.x * 8 + (tid >> 5);
    if (node >= N_NODES) return;
    int lane = tid & 31;
    int s = off[node], e = off[node + 1];
    float4 acc = make_float4(0.f, 0.f, 0.f, 0.f);
    const float4* vlin4 = (const float4*)vlin;

    for (int base = s; base < e; base += 32) {
        int m = min(32, e - base);
        int mj = (lane < m) ? jt[base + lane] : 0;
        float mc = (lane < m) ? cs[base + lane] : 0.f;
        int t = 0;
        for (; t + 4 <= m; t += 4) {
            int jv0 = __shfl_sync(0xffffffffu, mj, t);
            int jv1 = __shfl_sync(0xffffffffu, mj, t + 1);
            int jv2 = __shfl_sync(0xffffffffu, mj, t + 2);
            int jv3 = __shfl_sync(0xffffffffu, mj, t + 3);
            float c0 = __shfl_sync(0xffffffffu, mc, t);
            float c1 = __shfl_sync(0xffffffffu, mc, t + 1);
            float c2 = __shfl_sync(0xffffffffu, mc, t + 2);
            float c3 = __shfl_sync(0xffffffffu, mc, t + 3);
            float4 x0 = __ldg(vlin4 + (size_t)(jv0 & 0x07FFFFFF) * 32 + lane);
            float4 x1 = __ldg(vlin4 + (size_t)(jv1 & 0x07FFFFFF) * 32 + lane);
            float4 x2 = __ldg(vlin4 + (size_t)(jv2 & 0x07FFFFFF) * 32 + lane);
            float4 x3 = __ldg(vlin4 + (size_t)(jv3 & 0x07FFFFFF) * 32 + lane);
            float4 w0 = ws[(jv0 >> 27) * 32 + lane];
            float4 w1 = ws[(jv1 >> 27) * 32 + lane];
            float4 w2 = ws[(jv2 >> 27) * 32 + lane];
            float4 w3 = ws[(jv3 >> 27) * 32 + lane];
            acc.x += x0.x * w0.x * c0; acc.y += x0.y * w0.y * c0;
            acc.z += x0.z * w0.z * c0; acc.w += x0.w * w0.w * c0;
            acc.x += x1.x * w1.x * c1; acc.y += x1.y * w1.y * c1;
            acc.z += x1.z * w1.z * c1; acc.w += x1.w * w1.w * c1;
            acc.x += x2.x * w2.x * c2; acc.y += x2.y * w2.y * c2;
            acc.z += x2.z * w2.z * c2; acc.w += x2.w * w2.w * c2;
            acc.x += x3.x * w3.x * c3; acc.y += x3.y * w3.y * c3;
            acc.z += x3.z * w3.z * c3; acc.w += x3.w * w3.w * c3;
        }
        for (; t < m; t++) {
            int jv = __shfl_sync(0xffffffffu, mj, t);
            float c = __shfl_sync(0xffffffffu, mc, t);
            float4 x = __ldg(vlin4 + (size_t)(jv & 0x07FFFFFF) * 32 + lane);
            float4 w = ws[(jv >> 27) * 32 + lane];
            acc.x += x.x * w.x * c;
            acc.y += x.y * w.y * c;
            acc.z += x.z * w.z * c;
            acc.w += x.w * w.w * c;
        }
    }
    ((float4*)agg)[(size_t)node * 32 + lane] = acc;
}

// ---------------- launch ----------------
extern "C" void kernel_launch(void* const* d_in, const int* in_sizes, int n_in,
                              void* d_out, int out_size) {
    const float* z        = (const float*)d_in[0];
    const float* dist     = (const float*)d_in[1];
    const int*   ei       = (const int*)d_in[2];
    const float* init_w   = (const float*)d_in[3];
    const float* init_b   = (const float*)d_in[4];
    const float* e_lin_w[2] = {(const float*)d_in[5],  (const float*)d_in[14]};
    const float* e_m0_w[2]  = {(const float*)d_in[6],  (const float*)d_in[15]};
    const float* e_m0_b[2]  = {(const float*)d_in[7],  (const float*)d_in[16]};
    const float* e_m2_w[2]  = {(const float*)d_in[8],  (const float*)d_in[17]};
    const float* e_m2_b[2]  = {(const float*)d_in[9],  (const float*)d_in[18]};
    const float* v_l1_w[2]  = {(const float*)d_in[10], (const float*)d_in[19]};
    const float* v_l1_b[2]  = {(const float*)d_in[11], (const float*)d_in[20]};
    const float* v_l2_w[2]  = {(const float*)d_in[12], (const float*)d_in[21]};
    const float* v_l2_b[2]  = {(const float*)d_in[13], (const float*)d_in[22]};
    const float* u_l1_w   = (const float*)d_in[23];
    const float* u_l1_b   = (const float*)d_in[24];
    const float* u_l2_w   = (const float*)d_in[25];
    const float* u_l2_b   = (const float*)d_in[26];
    float* out = (float*)d_out;

    float *v, *vlin, *agg, *wtab, *cs;
    uint32_t* wpk;
    int *cnt, *off, *pos, *bsum, *jt;
    cudaGetSymbolAddress((void**)&v,    g_v);
    cudaGetSymbolAddress((void**)&vlin, g_vlin);
    cudaGetSymbolAddress((void**)&agg,  g_agg);
    cudaGetSymbolAddress((void**)&wtab, g_wtab);
    cudaGetSymbolAddress((void**)&wpk,  g_wpk);
    cudaGetSymbolAddress((void**)&cnt,  g_cnt);
    cudaGetSymbolAddress((void**)&off,  g_off);
    cudaGetSymbolAddress((void**)&pos,  g_pos);
    cudaGetSymbolAddress((void**)&bsum, g_bsum);
    cudaGetSymbolAddress((void**)&jt,   g_jt);
    cudaGetSymbolAddress((void**)&cs,   g_cs);

    cudaFuncSetAttribute((const void*)gemm0_fused,
                         cudaFuncAttributeMaxDynamicSharedMemorySize, TCG_SMEM);
    cudaFuncSetAttribute((const void*)mlp_fused,
                         cudaFuncAttributeMaxDynamicSharedMemorySize, TCG_SMEM);
    cudaFuncSetAttribute((const void*)mlp_readout_fused,
                         cudaFuncAttributeMaxDynamicSharedMemorySize, TCG_SMEM);

    const int egrid = (N_EDGES + 255) / 256;
    const int ngrid = (N_NODES + 255) / 256;
    const uint32_t* wm[7];  // 0:e_lin0 1:l1_0 2:l2_0 3:e_lin1 4:l1_1 5:l2_1 6:u1
    for (int i = 0; i < 7; i++) wm[i] = wpk + (size_t)i * WIMG_U32;

    table_kernel<<<2 * NBINS, H>>>(e_m0_w[0], e_m0_b[0], e_m2_w[0], e_m2_b[0],      // 0
                                   e_m0_w[1], e_m0_b[1], e_m2_w[1], e_m2_b[1], wtab);
    {
        dim3 wg(32, 7);
        wsplit_kernel<<<wg, 256>>>(e_lin_w[0], v_l1_w[0], v_l2_w[0],                 // 1
                                   e_lin_w[1], v_l1_w[1], v_l2_w[1], u_l1_w, wpk);
    }
    zero_cnt_kernel<<<ngrid, 256>>>(cnt);                                            // 2
    gemm0_fused<<<N_TILES, 512, TCG_SMEM>>>(z, init_w, init_b, wm[0],                // 3 <- profiled
                                            v, vlin, N_NODES);
    hist_kernel<<<egrid, 256>>>(ei, cnt);                                            // 4
    scan1_kernel<<<SCAN_BLOCKS, 256>>>(cnt, off, bsum);                              // 5
    scan2_kernel<<<1, 256>>>(bsum);                                                  // 6
    scan3_kernel<<<SCAN_BLOCKS, 256>>>(off, bsum, pos);                              // 7
    scatter_kernel<<<egrid, 256>>>(ei, dist, pos, jt, cs);                           // 8

    // layer 0: fused l1 -> ssp -> l2 (+v) -> vlin = v @ e_lin1
    agg_kernel<<<(N_NODES + 7) / 8, 256>>>(vlin, off, jt, cs, wtab, agg);            // 9
    mlp_fused<<<N_TILES, 512, TCG_SMEM>>>(agg, wm[1], v_l1_b[0],                     // 10
                                          wm[2], v_l2_b[0], v, wm[3], vlin, N_NODES);
    // layer 1 + readout fused
    agg_kernel<<<(N_NODES + 7) / 8, 256>>>(vlin, off, jt, cs, wtab + NBINS * H, agg);// 11
    mlp_readout_fused<<<N_TILES, 512, TCG_SMEM>>>(agg, wm[4], v_l1_b[1],             // 12
                                                  wm[5], v_l2_b[1], v,
                                                  wm[6], u_l1_b, u_l2_w, u_l2_b,
                                                  out, N_NODES);
}